// round 8
// baseline (speedup 1.0000x reference)
#include <cuda_runtime.h>
#include <math.h>

#define D_MODEL 1024
#define D_STATE 16
#define D_CONV  4
#define D_INNER 2048
#define DT_RANK 64
#define NBLK    4
#define BATCH   2
#define SEQLEN  1024
#define M_TOK   (BATCH*SEQLEN)   // 2048 tokens
#define XD      96               // dt_rank + 2*d_state

// ---------------- scratch (no allocation allowed) ----------------
__device__ __align__(256) float g_h[M_TOK*D_MODEL];            // 8 MB
__device__ __align__(256) float g_xz[(size_t)M_TOK*2*D_INNER]; // 32 MB
__device__ __align__(256) float g_u[(size_t)M_TOK*D_INNER];    // 16 MB
__device__ __align__(256) float g_xdbl[M_TOK*XD];
__device__ __align__(256) float g_xdbl_part[4*M_TOK*XD];
__device__ __align__(256) float g_dt[(size_t)M_TOK*D_INNER];   // 16 MB
__device__ __align__(256) float g_yg[(size_t)M_TOK*D_INNER];   // 16 MB

__device__ __forceinline__ float siluf(float v) {
    return v / (1.f + __expf(-v));
}

// ---------------- generic fp32 SGEMM:  C[M,N] = A[M,K(lda)] * W[N,K]^T ----------------
// EPI: 0 = none, 1 = softplus(x + bias[n]), 2 = silu
// SPLIT: grid.z splits K; each split writes its own partial buffer slice.
template<int BM,int BN,int BK,int TM,int TN,int EPI,bool SPLIT>
__global__ void __launch_bounds__((BM/TM)*(BN/TN), 2) sgemm_k(
    const float* __restrict__ A, const float* __restrict__ W,
    const float* __restrict__ bias, float* __restrict__ C,
    int M, int N, int K, int lda, int ksplit)
{
    constexpr int THREADS = (BM/TM)*(BN/TN);
    __shared__ float As[BK][BM];
    __shared__ float Bs[BK][BN];

    const int bm = blockIdx.y * BM;
    const int bn = blockIdx.x * BN;
    int k0 = 0, kend = K;
    if (SPLIT) {
        k0 = blockIdx.z * ksplit;
        kend = k0 + ksplit;
        C += (size_t)blockIdx.z * (size_t)M * N;
    }

    const int tid = threadIdx.x;
    const int tx = tid % (BN/TN);
    const int ty = tid / (BN/TN);

    float acc[TM][TN];
#pragma unroll
    for (int i = 0; i < TM; i++)
#pragma unroll
        for (int j = 0; j < TN; j++) acc[i][j] = 0.f;

    for (int kt = k0; kt < kend; kt += BK) {
        // load A tile (BM x BK), transpose into As[k][m]
#pragma unroll
        for (int idx = tid; idx < BM*(BK/4); idx += THREADS) {
            int row = idx / (BK/4), kq = idx % (BK/4);
            float4 v = *reinterpret_cast<const float4*>(A + (size_t)(bm+row)*lda + kt + kq*4);
            As[kq*4+0][row] = v.x; As[kq*4+1][row] = v.y;
            As[kq*4+2][row] = v.z; As[kq*4+3][row] = v.w;
        }
        // load W tile (BN x BK), transpose into Bs[k][n]
#pragma unroll
        for (int idx = tid; idx < BN*(BK/4); idx += THREADS) {
            int col = idx / (BK/4), kq = idx % (BK/4);
            float4 v = *reinterpret_cast<const float4*>(W + (size_t)(bn+col)*K + kt + kq*4);
            Bs[kq*4+0][col] = v.x; Bs[kq*4+1][col] = v.y;
            Bs[kq*4+2][col] = v.z; Bs[kq*4+3][col] = v.w;
        }
        __syncthreads();
#pragma unroll
        for (int k = 0; k < BK; k++) {
            float a[TM], b[TN];
#pragma unroll
            for (int i = 0; i < TM; i++) a[i] = As[k][ty*TM + i];
#pragma unroll
            for (int j = 0; j < TN; j++) b[j] = Bs[k][tx*TN + j];
#pragma unroll
            for (int i = 0; i < TM; i++)
#pragma unroll
                for (int j = 0; j < TN; j++)
                    acc[i][j] = fmaf(a[i], b[j], acc[i][j]);
        }
        __syncthreads();
    }

#pragma unroll
    for (int i = 0; i < TM; i++) {
        int m = bm + ty*TM + i;
#pragma unroll
        for (int j = 0; j < TN; j++) {
            int n = bn + tx*TN + j;
            float v = acc[i][j];
            if (EPI == 1) {                       // softplus(x + bias)
                v += bias[n];
                v = fmaxf(v, 0.f) + log1pf(__expf(-fabsf(v)));
            }
            if (EPI == 2) {                       // silu
                v = siluf(v);
            }
            C[(size_t)m * N + n] = v;
        }
    }
}

// ---------------- embedding: h[m,d] = x[m]*emb_w[d] + emb_b[d] ----------------
__global__ void embed_k(const float* __restrict__ x, const float* __restrict__ ew,
                        const float* __restrict__ eb, float* __restrict__ h)
{
    int i = blockIdx.x * blockDim.x + threadIdx.x;  // M_TOK*D_MODEL
    int d = i % D_MODEL, m = i / D_MODEL;
    h[i] = fmaf(x[m], ew[d], eb[d]);
}

// ---------------- causal depthwise conv (width 4) + silu ----------------
__global__ void conv_silu_k(const float* __restrict__ xz, const float* __restrict__ cw,
                            const float* __restrict__ cb, float* __restrict__ u)
{
    int i = blockIdx.x * blockDim.x + threadIdx.x;  // M_TOK*D_INNER
    int d = i % D_INNER;
    int m = i / D_INNER;
    int t = m % SEQLEN;
    float acc = cb[d];
#pragma unroll
    for (int k = 0; k < D_CONV; k++) {
        int tt = t - (D_CONV-1) + k;
        if (tt >= 0)
            acc = fmaf(cw[d*D_CONV + k], xz[(size_t)(m-(D_CONV-1)+k)*(2*D_INNER) + d], acc);
    }
    u[i] = siluf(acc);
}

// ---------------- reduce split-K partials ----------------
__global__ void reduce4_k(float* __restrict__ out, const float* __restrict__ part, int n)
{
    int i = blockIdx.x * blockDim.x + threadIdx.x;
    if (i < n)
        out[i] = (part[i] + part[n + i]) + (part[2*n + i] + part[3*n + i]);
}

// ---------------- selective scan + gating fused ----------------
// block: 512 threads = 32 d-channels x 16 states; grid (D_INNER/32, BATCH)
#define SC_D 32
#define SC_T 64
__global__ void __launch_bounds__(512) scan_k(
    const float* __restrict__ dt, const float* __restrict__ u,
    const float* __restrict__ xdbl, const float* __restrict__ xz,
    const float* __restrict__ A_log, const float* __restrict__ Dp,
    float* __restrict__ yg)
{
    __shared__ float s_dt[SC_T][SC_D];
    __shared__ float s_u [SC_T][SC_D];
    __shared__ float s_z [SC_T][SC_D];
    __shared__ float s_B [SC_T][D_STATE];
    __shared__ float s_C [SC_T][D_STATE];

    const int b  = blockIdx.y;
    const int d0 = blockIdx.x * SC_D;
    const int tid = threadIdx.x;
    const int n  = tid & 15;
    const int dl = tid >> 4;
    const int d  = d0 + dl;

    const float Aval = -__expf(A_log[d*D_STATE + n]);
    const float Dval = Dp[d];
    float s = 0.f;
    const size_t rowbase = (size_t)b * SEQLEN;

    for (int t0 = 0; t0 < SEQLEN; t0 += SC_T) {
        for (int idx = tid; idx < SC_T*SC_D; idx += 512) {
            int tl = idx / SC_D, dd = idx % SC_D;
            size_t r = rowbase + t0 + tl;
            s_dt[tl][dd] = dt[r*D_INNER + d0 + dd];
            s_u [tl][dd] = u [r*D_INNER + d0 + dd];
            s_z [tl][dd] = xz[r*(2*D_INNER) + D_INNER + d0 + dd];
        }
        for (int idx = tid; idx < SC_T*D_STATE; idx += 512) {
            int tl = idx / D_STATE, nn = idx % D_STATE;
            size_t r = rowbase + t0 + tl;
            s_B[tl][nn] = xdbl[r*XD + DT_RANK + nn];
            s_C[tl][nn] = xdbl[r*XD + DT_RANK + D_STATE + nn];
        }
        __syncthreads();

        for (int tl = 0; tl < SC_T; tl++) {
            float dtv = s_dt[tl][dl];
            float uv  = s_u [tl][dl];
            float dA  = __expf(dtv * Aval);
            s = fmaf(dA, s, dtv * uv * s_B[tl][n]);
            float y = s * s_C[tl][n];
#pragma unroll
            for (int off = 8; off; off >>= 1)
                y += __shfl_xor_sync(0xffffffffu, y, off, 16);
            if (n == 0) {
                float zv = s_z[tl][dl];
                float yy = fmaf(Dval, uv, y);
                yg[(rowbase + t0 + tl)*D_INNER + d] = yy * siluf(zv);
            }
        }
        __syncthreads();
    }
}

// ---------------- host ----------------
extern "C" void kernel_launch(void* const* d_in, const int* in_sizes, int n_in,
                              void* d_out, int out_size)
{
    const float* x          = (const float*)d_in[0];
    const float* emb_w      = (const float*)d_in[1];
    const float* emb_b      = (const float*)d_in[2];
    const float* in_proj_w  = (const float*)d_in[3];
    const float* conv_w     = (const float*)d_in[4];
    const float* conv_b     = (const float*)d_in[5];
    const float* x_proj_w   = (const float*)d_in[6];
    const float* dt_proj_w  = (const float*)d_in[7];
    const float* dt_proj_b  = (const float*)d_in[8];
    const float* A_log      = (const float*)d_in[9];
    const float* D_param    = (const float*)d_in[10];
    const float* out_proj_w = (const float*)d_in[11];
    float* out = (float*)d_out;

    float *ph, *pxz, *pu, *pxdbl, *pxpart, *pdt, *pyg;
    cudaGetSymbolAddress((void**)&ph,     g_h);
    cudaGetSymbolAddress((void**)&pxz,    g_xz);
    cudaGetSymbolAddress((void**)&pu,     g_u);
    cudaGetSymbolAddress((void**)&pxdbl,  g_xdbl);
    cudaGetSymbolAddress((void**)&pxpart, g_xdbl_part);
    cudaGetSymbolAddress((void**)&pdt,    g_dt);
    cudaGetSymbolAddress((void**)&pyg,    g_yg);

    embed_k<<<(M_TOK*D_MODEL)/256, 256>>>(x, emb_w, emb_b, ph);

    for (int i = 0; i < NBLK; i++) {
        float* h_out = (i == NBLK-1) ? out : ph;

        // GEMM1: xz = h @ in_proj_w^T   [2048 x 4096 x 1024]
        sgemm_k<128,128,16,8,8,0,false>
            <<<dim3((2*D_INNER)/128, M_TOK/128), 256>>>(
                ph, in_proj_w + (size_t)i*2*D_INNER*D_MODEL, nullptr, pxz,
                M_TOK, 2*D_INNER, D_MODEL, D_MODEL, 0);

        // depthwise conv + silu -> u
        conv_silu_k<<<(M_TOK*D_INNER)/256, 256>>>(
            pxz, conv_w + (size_t)i*D_INNER*D_CONV, conv_b + (size_t)i*D_INNER, pu);

        // GEMM2 (split-K x4): x_dbl partials = u @ x_proj_w^T   [2048 x 96 x 2048]
        sgemm_k<64,96,16,4,6,0,true>
            <<<dim3(1, M_TOK/64, 4), 256>>>(
                pu, x_proj_w + (size_t)i*XD*D_INNER, nullptr, pxpart,
                M_TOK, XD, D_INNER, D_INNER, D_INNER/4);
        reduce4_k<<<(M_TOK*XD + 255)/256, 256>>>(pxdbl, pxpart, M_TOK*XD);

        // GEMM3: dt = softplus(dt_lo @ dt_proj_w^T + b)   [2048 x 2048 x 64], lda=96
        sgemm_k<128,128,16,8,8,1,false>
            <<<dim3(D_INNER/128, M_TOK/128), 256>>>(
                pxdbl, dt_proj_w + (size_t)i*D_INNER*DT_RANK,
                dt_proj_b + (size_t)i*D_INNER, pdt,
                M_TOK, D_INNER, DT_RANK, XD, 0);

        // selective scan + (y + D*u)*silu(z) fused -> yg
        scan_k<<<dim3(D_INNER/SC_D, BATCH), 512>>>(
            pdt, pu, pxdbl, pxz,
            A_log + (size_t)i*D_INNER*D_STATE, D_param + (size_t)i*D_INNER, pyg);

        // GEMM4: h' = silu(yg @ out_proj_w^T)   [2048 x 1024 x 2048]
        sgemm_k<128,128,16,8,8,2,false>
            <<<dim3(D_MODEL/128, M_TOK/128), 256>>>(
                pyg, out_proj_w + (size_t)i*D_MODEL*D_INNER, nullptr, h_out,
                M_TOK, D_MODEL, D_INNER, D_INNER, 0);
    }
    (void)in_sizes; (void)n_in; (void)out_size;
}

// round 9
// speedup vs baseline: 1.0533x; 1.0533x over previous
#include <cuda_runtime.h>
#include <math.h>

#define D_MODEL 1024
#define D_STATE 16
#define D_CONV  4
#define D_INNER 2048
#define DT_RANK 64
#define NBLK    4
#define BATCH   2
#define SEQLEN  1024
#define M_TOK   (BATCH*SEQLEN)   // 2048 tokens
#define XD      96               // dt_rank + 2*d_state

// ---------------- scratch (no allocation allowed) ----------------
__device__ __align__(256) float g_h[M_TOK*D_MODEL];            // 8 MB
__device__ __align__(256) float g_xz[(size_t)M_TOK*2*D_INNER]; // 32 MB
__device__ __align__(256) float g_u[(size_t)M_TOK*D_INNER];    // 16 MB
__device__ __align__(256) float g_xdbl[M_TOK*XD];
__device__ __align__(256) float g_xdbl_part[4*M_TOK*XD];
__device__ __align__(256) float g_dt[(size_t)M_TOK*D_INNER];   // 16 MB
__device__ __align__(256) float g_yg[(size_t)M_TOK*D_INNER];   // 16 MB

__device__ __forceinline__ float siluf(float v) {
    return v / (1.f + __expf(-v));
}

// ---- packed fp32x2 helpers (sm_100+ FFMA2 — only reachable via PTX) ----
__device__ __forceinline__ unsigned long long pk2(float x, float y) {
    unsigned long long r;
    asm("mov.b64 %0, {%1, %2};" : "=l"(r) : "f"(x), "f"(y));
    return r;
}
__device__ __forceinline__ void ffma2(unsigned long long& d,
                                      unsigned long long a,
                                      unsigned long long b) {
    asm("fma.rn.f32x2 %0, %1, %2, %0;" : "+l"(d) : "l"(a), "l"(b));
}
__device__ __forceinline__ float2 unpk2(unsigned long long v) {
    float2 r;
    asm("mov.b64 {%0, %1}, %2;" : "=f"(r.x), "=f"(r.y) : "l"(v));
    return r;
}

// ---------------- fp32 SGEMM with packed FFMA2 core ----------------
//  C[M,N] = A[M,K(lda)] * W[N,K]^T
// EPI: 0 = none, 1 = softplus(x + bias[n]), 2 = silu
// SPLIT: grid.z splits K; each split writes its own partial buffer slice.
template<int BM,int BN,int BK,int TM,int TN,int EPI,bool SPLIT>
__global__ void __launch_bounds__((BM/TM)*(BN/TN), 2) sgemm_k(
    const float* __restrict__ A, const float* __restrict__ W,
    const float* __restrict__ bias, float* __restrict__ C,
    int M, int N, int K, int lda, int ksplit)
{
    constexpr int THREADS = (BM/TM)*(BN/TN);
    constexpr int TN2 = TN/2;
    static_assert(TN % 2 == 0, "TN must be even for f32x2 packing");
    __shared__ float As[BK][BM];
    __shared__ float Bs[BK][BN];

    const int bm = blockIdx.y * BM;
    const int bn = blockIdx.x * BN;
    int k0 = 0, kend = K;
    if (SPLIT) {
        k0 = blockIdx.z * ksplit;
        kend = k0 + ksplit;
        C += (size_t)blockIdx.z * (size_t)M * N;
    }

    const int tid = threadIdx.x;
    const int tx = tid % (BN/TN);
    const int ty = tid / (BN/TN);

    unsigned long long acc[TM][TN2];
#pragma unroll
    for (int i = 0; i < TM; i++)
#pragma unroll
        for (int j = 0; j < TN2; j++) acc[i][j] = 0ull;   // bit pattern {0.f,0.f}

    for (int kt = k0; kt < kend; kt += BK) {
        // load A tile (BM x BK), transpose into As[k][m]
#pragma unroll
        for (int idx = tid; idx < BM*(BK/4); idx += THREADS) {
            int row = idx / (BK/4), kq = idx % (BK/4);
            float4 v = *reinterpret_cast<const float4*>(A + (size_t)(bm+row)*lda + kt + kq*4);
            As[kq*4+0][row] = v.x; As[kq*4+1][row] = v.y;
            As[kq*4+2][row] = v.z; As[kq*4+3][row] = v.w;
        }
        // load W tile (BN x BK), transpose into Bs[k][n]
#pragma unroll
        for (int idx = tid; idx < BN*(BK/4); idx += THREADS) {
            int col = idx / (BK/4), kq = idx % (BK/4);
            float4 v = *reinterpret_cast<const float4*>(W + (size_t)(bn+col)*K + kt + kq*4);
            Bs[kq*4+0][col] = v.x; Bs[kq*4+1][col] = v.y;
            Bs[kq*4+2][col] = v.z; Bs[kq*4+3][col] = v.w;
        }
        __syncthreads();
#pragma unroll
        for (int k = 0; k < BK; k++) {
            float a[TM];
#pragma unroll
            for (int i = 0; i < TM; i++) a[i] = As[k][ty*TM + i];
            unsigned long long b2[TN2];
#pragma unroll
            for (int j = 0; j < TN2; j++)
                b2[j] = *reinterpret_cast<const unsigned long long*>(&Bs[k][tx*TN + 2*j]);
#pragma unroll
            for (int i = 0; i < TM; i++) {
                unsigned long long ad = pk2(a[i], a[i]);
#pragma unroll
                for (int j = 0; j < TN2; j++)
                    ffma2(acc[i][j], ad, b2[j]);
            }
        }
        __syncthreads();
    }

#pragma unroll
    for (int i = 0; i < TM; i++) {
        int m = bm + ty*TM + i;
        float* crow = C + (size_t)m * N + bn + tx*TN;
#pragma unroll
        for (int j = 0; j < TN2; j++) {
            float2 v = unpk2(acc[i][j]);
            if (EPI == 1) {                       // softplus(x + bias)
                int n = bn + tx*TN + 2*j;
                v.x += bias[n];
                v.y += bias[n+1];
                v.x = fmaxf(v.x, 0.f) + log1pf(__expf(-fabsf(v.x)));
                v.y = fmaxf(v.y, 0.f) + log1pf(__expf(-fabsf(v.y)));
            }
            if (EPI == 2) {                       // silu
                v.x = siluf(v.x);
                v.y = siluf(v.y);
            }
            *reinterpret_cast<float2*>(crow + 2*j) = v;
        }
    }
}

// ---------------- embedding: h[m,d] = x[m]*emb_w[d] + emb_b[d] ----------------
__global__ void embed_k(const float* __restrict__ x, const float* __restrict__ ew,
                        const float* __restrict__ eb, float* __restrict__ h)
{
    int i = blockIdx.x * blockDim.x + threadIdx.x;  // M_TOK*D_MODEL
    int d = i % D_MODEL, m = i / D_MODEL;
    h[i] = fmaf(x[m], ew[d], eb[d]);
}

// ---------------- causal depthwise conv (width 4) + silu ----------------
__global__ void conv_silu_k(const float* __restrict__ xz, const float* __restrict__ cw,
                            const float* __restrict__ cb, float* __restrict__ u)
{
    int i = blockIdx.x * blockDim.x + threadIdx.x;  // M_TOK*D_INNER
    int d = i % D_INNER;
    int m = i / D_INNER;
    int t = m % SEQLEN;
    float acc = cb[d];
#pragma unroll
    for (int k = 0; k < D_CONV; k++) {
        int tt = t - (D_CONV-1) + k;
        if (tt >= 0)
            acc = fmaf(cw[d*D_CONV + k], xz[(size_t)(m-(D_CONV-1)+k)*(2*D_INNER) + d], acc);
    }
    u[i] = siluf(acc);
}

// ---------------- reduce split-K partials ----------------
__global__ void reduce4_k(float* __restrict__ out, const float* __restrict__ part, int n)
{
    int i = blockIdx.x * blockDim.x + threadIdx.x;
    if (i < n)
        out[i] = (part[i] + part[n + i]) + (part[2*n + i] + part[3*n + i]);
}

// ---------------- selective scan + gating fused ----------------
// block: 512 threads = 32 d-channels x 16 states; grid (D_INNER/32, BATCH)
#define SC_D 32
#define SC_T 64
__global__ void __launch_bounds__(512) scan_k(
    const float* __restrict__ dt, const float* __restrict__ u,
    const float* __restrict__ xdbl, const float* __restrict__ xz,
    const float* __restrict__ A_log, const float* __restrict__ Dp,
    float* __restrict__ yg)
{
    __shared__ float s_dt[SC_T][SC_D];
    __shared__ float s_u [SC_T][SC_D];
    __shared__ float s_z [SC_T][SC_D];
    __shared__ float s_B [SC_T][D_STATE];
    __shared__ float s_C [SC_T][D_STATE];

    const int b  = blockIdx.y;
    const int d0 = blockIdx.x * SC_D;
    const int tid = threadIdx.x;
    const int n  = tid & 15;
    const int dl = tid >> 4;
    const int d  = d0 + dl;

    const float Aval = -__expf(A_log[d*D_STATE + n]);
    const float Dval = Dp[d];
    float s = 0.f;
    const size_t rowbase = (size_t)b * SEQLEN;

    for (int t0 = 0; t0 < SEQLEN; t0 += SC_T) {
        for (int idx = tid; idx < SC_T*SC_D; idx += 512) {
            int tl = idx / SC_D, dd = idx % SC_D;
            size_t r = rowbase + t0 + tl;
            s_dt[tl][dd] = dt[r*D_INNER + d0 + dd];
            s_u [tl][dd] = u [r*D_INNER + d0 + dd];
            s_z [tl][dd] = xz[r*(2*D_INNER) + D_INNER + d0 + dd];
        }
        for (int idx = tid; idx < SC_T*D_STATE; idx += 512) {
            int tl = idx / D_STATE, nn = idx % D_STATE;
            size_t r = rowbase + t0 + tl;
            s_B[tl][nn] = xdbl[r*XD + DT_RANK + nn];
            s_C[tl][nn] = xdbl[r*XD + DT_RANK + D_STATE + nn];
        }
        __syncthreads();

        for (int tl = 0; tl < SC_T; tl++) {
            float dtv = s_dt[tl][dl];
            float uv  = s_u [tl][dl];
            float dA  = __expf(dtv * Aval);
            s = fmaf(dA, s, dtv * uv * s_B[tl][n]);
            float y = s * s_C[tl][n];
#pragma unroll
            for (int off = 8; off; off >>= 1)
                y += __shfl_xor_sync(0xffffffffu, y, off, 16);
            if (n == 0) {
                float zv = s_z[tl][dl];
                float yy = fmaf(Dval, uv, y);
                yg[(rowbase + t0 + tl)*D_INNER + d] = yy * siluf(zv);
            }
        }
        __syncthreads();
    }
}

// ---------------- host ----------------
extern "C" void kernel_launch(void* const* d_in, const int* in_sizes, int n_in,
                              void* d_out, int out_size)
{
    const float* x          = (const float*)d_in[0];
    const float* emb_w      = (const float*)d_in[1];
    const float* emb_b      = (const float*)d_in[2];
    const float* in_proj_w  = (const float*)d_in[3];
    const float* conv_w     = (const float*)d_in[4];
    const float* conv_b     = (const float*)d_in[5];
    const float* x_proj_w   = (const float*)d_in[6];
    const float* dt_proj_w  = (const float*)d_in[7];
    const float* dt_proj_b  = (const float*)d_in[8];
    const float* A_log      = (const float*)d_in[9];
    const float* D_param    = (const float*)d_in[10];
    const float* out_proj_w = (const float*)d_in[11];
    float* out = (float*)d_out;

    float *ph, *pxz, *pu, *pxdbl, *pxpart, *pdt, *pyg;
    cudaGetSymbolAddress((void**)&ph,     g_h);
    cudaGetSymbolAddress((void**)&pxz,    g_xz);
    cudaGetSymbolAddress((void**)&pu,     g_u);
    cudaGetSymbolAddress((void**)&pxdbl,  g_xdbl);
    cudaGetSymbolAddress((void**)&pxpart, g_xdbl_part);
    cudaGetSymbolAddress((void**)&pdt,    g_dt);
    cudaGetSymbolAddress((void**)&pyg,    g_yg);

    embed_k<<<(M_TOK*D_MODEL)/256, 256>>>(x, emb_w, emb_b, ph);

    for (int i = 0; i < NBLK; i++) {
        float* h_out = (i == NBLK-1) ? out : ph;

        // GEMM1: xz = h @ in_proj_w^T   [2048 x 4096 x 1024]
        sgemm_k<128,128,16,8,8,0,false>
            <<<dim3((2*D_INNER)/128, M_TOK/128), 256>>>(
                ph, in_proj_w + (size_t)i*2*D_INNER*D_MODEL, nullptr, pxz,
                M_TOK, 2*D_INNER, D_MODEL, D_MODEL, 0);

        // depthwise conv + silu -> u
        conv_silu_k<<<(M_TOK*D_INNER)/256, 256>>>(
            pxz, conv_w + (size_t)i*D_INNER*D_CONV, conv_b + (size_t)i*D_INNER, pu);

        // GEMM2 (split-K x4): x_dbl partials = u @ x_proj_w^T   [2048 x 96 x 2048]
        sgemm_k<64,96,16,4,6,0,true>
            <<<dim3(1, M_TOK/64, 4), 256>>>(
                pu, x_proj_w + (size_t)i*XD*D_INNER, nullptr, pxpart,
                M_TOK, XD, D_INNER, D_INNER, D_INNER/4);
        reduce4_k<<<(M_TOK*XD + 255)/256, 256>>>(pxdbl, pxpart, M_TOK*XD);

        // GEMM3: dt = softplus(dt_lo @ dt_proj_w^T + b)   [2048 x 2048 x 64], lda=96
        sgemm_k<128,128,16,8,8,1,false>
            <<<dim3(D_INNER/128, M_TOK/128), 256>>>(
                pxdbl, dt_proj_w + (size_t)i*D_INNER*DT_RANK,
                dt_proj_b + (size_t)i*D_INNER, pdt,
                M_TOK, D_INNER, DT_RANK, XD, 0);

        // selective scan + (y + D*u)*silu(z) fused -> yg
        scan_k<<<dim3(D_INNER/SC_D, BATCH), 512>>>(
            pdt, pu, pxdbl, pxz,
            A_log + (size_t)i*D_INNER*D_STATE, D_param + (size_t)i*D_INNER, pyg);

        // GEMM4: h' = silu(yg @ out_proj_w^T)   [2048 x 1024 x 2048]
        sgemm_k<128,128,16,8,8,2,false>
            <<<dim3(D_MODEL/128, M_TOK/128), 256>>>(
                pyg, out_proj_w + (size_t)i*D_MODEL*D_INNER, nullptr, h_out,
                M_TOK, D_MODEL, D_INNER, D_INNER, 0);
    }
    (void)in_sizes; (void)n_in; (void)out_size;
}

// round 10
// speedup vs baseline: 1.0539x; 1.0005x over previous
#include <cuda_runtime.h>
#include <math.h>

#define D_MODEL 1024
#define D_STATE 16
#define D_CONV  4
#define D_INNER 2048
#define DT_RANK 64
#define NBLK    4
#define BATCH   2
#define SEQLEN  1024
#define M_TOK   (BATCH*SEQLEN)   // 2048 tokens
#define XD      96               // dt_rank + 2*d_state

// ---------------- scratch (no allocation allowed) ----------------
__device__ __align__(256) float g_h[M_TOK*D_MODEL];            // 8 MB
__device__ __align__(256) float g_xz[(size_t)M_TOK*2*D_INNER]; // 32 MB
__device__ __align__(256) float g_u[(size_t)M_TOK*D_INNER];    // 16 MB
__device__ __align__(256) float g_xdbl[M_TOK*XD];
__device__ __align__(256) float g_xdbl_part[4*M_TOK*XD];
__device__ __align__(256) float g_dt[(size_t)M_TOK*D_INNER];   // 16 MB
__device__ __align__(256) float g_yg[(size_t)M_TOK*D_INNER];   // 16 MB

__device__ __forceinline__ float siluf(float v) {
    return v / (1.f + __expf(-v));
}

// ---- packed fp32x2 helpers (sm_100+ FFMA2 — only reachable via PTX) ----
__device__ __forceinline__ unsigned long long pk2(float x, float y) {
    unsigned long long r;
    asm("mov.b64 %0, {%1, %2};" : "=l"(r) : "f"(x), "f"(y));
    return r;
}
__device__ __forceinline__ void ffma2(unsigned long long& d,
                                      unsigned long long a,
                                      unsigned long long b) {
    asm("fma.rn.f32x2 %0, %1, %2, %0;" : "+l"(d) : "l"(a), "l"(b));
}
__device__ __forceinline__ float2 unpk2(unsigned long long v) {
    float2 r;
    asm("mov.b64 {%0, %1}, %2;" : "=f"(r.x), "=f"(r.y) : "l"(v));
    return r;
}

// ---------------- fp32 SGEMM with packed FFMA2 core ----------------
//  C[M,N] = A[M,K(lda)] * W[N,K]^T
// EPI: 0 = none, 1 = softplus(x + bias[n]), 2 = silu
// SPLIT: grid.z splits K; each split writes its own partial buffer slice.
template<int BM,int BN,int BK,int TM,int TN,int EPI,bool SPLIT>
__global__ void __launch_bounds__((BM/TM)*(BN/TN), 2) sgemm_k(
    const float* __restrict__ A, const float* __restrict__ W,
    const float* __restrict__ bias, float* __restrict__ C,
    int M, int N, int K, int lda, int ksplit)
{
    constexpr int THREADS = (BM/TM)*(BN/TN);
    constexpr int TN2 = TN/2;
    static_assert(TN % 2 == 0, "TN must be even for f32x2 packing");
    __shared__ float As[BK][BM];
    __shared__ float Bs[BK][BN];

    const int bm = blockIdx.y * BM;
    const int bn = blockIdx.x * BN;
    int k0 = 0, kend = K;
    if (SPLIT) {
        k0 = blockIdx.z * ksplit;
        kend = k0 + ksplit;
        C += (size_t)blockIdx.z * (size_t)M * N;
    }

    const int tid = threadIdx.x;
    const int tx = tid % (BN/TN);
    const int ty = tid / (BN/TN);

    unsigned long long acc[TM][TN2];
#pragma unroll
    for (int i = 0; i < TM; i++)
#pragma unroll
        for (int j = 0; j < TN2; j++) acc[i][j] = 0ull;   // bit pattern {0.f,0.f}

    for (int kt = k0; kt < kend; kt += BK) {
        // load A tile (BM x BK), transpose into As[k][m]
#pragma unroll
        for (int idx = tid; idx < BM*(BK/4); idx += THREADS) {
            int row = idx / (BK/4), kq = idx % (BK/4);
            float4 v = *reinterpret_cast<const float4*>(A + (size_t)(bm+row)*lda + kt + kq*4);
            As[kq*4+0][row] = v.x; As[kq*4+1][row] = v.y;
            As[kq*4+2][row] = v.z; As[kq*4+3][row] = v.w;
        }
        // load W tile (BN x BK), transpose into Bs[k][n]
#pragma unroll
        for (int idx = tid; idx < BN*(BK/4); idx += THREADS) {
            int col = idx / (BK/4), kq = idx % (BK/4);
            float4 v = *reinterpret_cast<const float4*>(W + (size_t)(bn+col)*K + kt + kq*4);
            Bs[kq*4+0][col] = v.x; Bs[kq*4+1][col] = v.y;
            Bs[kq*4+2][col] = v.z; Bs[kq*4+3][col] = v.w;
        }
        __syncthreads();
#pragma unroll
        for (int k = 0; k < BK; k++) {
            float a[TM];
#pragma unroll
            for (int i = 0; i < TM; i++) a[i] = As[k][ty*TM + i];
            unsigned long long b2[TN2];
#pragma unroll
            for (int j = 0; j < TN2; j++)
                b2[j] = *reinterpret_cast<const unsigned long long*>(&Bs[k][tx*TN + 2*j]);
#pragma unroll
            for (int i = 0; i < TM; i++) {
                unsigned long long ad = pk2(a[i], a[i]);
#pragma unroll
                for (int j = 0; j < TN2; j++)
                    ffma2(acc[i][j], ad, b2[j]);
            }
        }
        __syncthreads();
    }

#pragma unroll
    for (int i = 0; i < TM; i++) {
        int m = bm + ty*TM + i;
        float* crow = C + (size_t)m * N + bn + tx*TN;
#pragma unroll
        for (int j = 0; j < TN2; j++) {
            float2 v = unpk2(acc[i][j]);
            if (EPI == 1) {                       // softplus(x + bias)
                int n = bn + tx*TN + 2*j;
                v.x += bias[n];
                v.y += bias[n+1];
                v.x = fmaxf(v.x, 0.f) + log1pf(__expf(-fabsf(v.x)));
                v.y = fmaxf(v.y, 0.f) + log1pf(__expf(-fabsf(v.y)));
            }
            if (EPI == 2) {                       // silu
                v.x = siluf(v.x);
                v.y = siluf(v.y);
            }
            *reinterpret_cast<float2*>(crow + 2*j) = v;
        }
    }
}

// ---------------- embedding: h[m,d] = x[m]*emb_w[d] + emb_b[d] ----------------
__global__ void embed_k(const float* __restrict__ x, const float* __restrict__ ew,
                        const float* __restrict__ eb, float* __restrict__ h)
{
    int i = blockIdx.x * blockDim.x + threadIdx.x;  // M_TOK*D_MODEL
    int d = i % D_MODEL, m = i / D_MODEL;
    h[i] = fmaf(x[m], ew[d], eb[d]);
}

// ---------------- causal depthwise conv (width 4) + silu ----------------
__global__ void conv_silu_k(const float* __restrict__ xz, const float* __restrict__ cw,
                            const float* __restrict__ cb, float* __restrict__ u)
{
    int i = blockIdx.x * blockDim.x + threadIdx.x;  // M_TOK*D_INNER
    int d = i % D_INNER;
    int m = i / D_INNER;
    int t = m % SEQLEN;
    float acc = cb[d];
#pragma unroll
    for (int k = 0; k < D_CONV; k++) {
        int tt = t - (D_CONV-1) + k;
        if (tt >= 0)
            acc = fmaf(cw[d*D_CONV + k], xz[(size_t)(m-(D_CONV-1)+k)*(2*D_INNER) + d], acc);
    }
    u[i] = siluf(acc);
}

// ---------------- reduce split-K partials ----------------
__global__ void reduce4_k(float* __restrict__ out, const float* __restrict__ part, int n)
{
    int i = blockIdx.x * blockDim.x + threadIdx.x;
    if (i < n)
        out[i] = (part[i] + part[n + i]) + (part[2*n + i] + part[3*n + i]);
}

// ---------------- selective scan + gating fused ----------------
// block: 512 threads = 32 d-channels x 16 states; grid (D_INNER/32, BATCH)
#define SC_D 32
#define SC_T 64
__global__ void __launch_bounds__(512) scan_k(
    const float* __restrict__ dt, const float* __restrict__ u,
    const float* __restrict__ xdbl, const float* __restrict__ xz,
    const float* __restrict__ A_log, const float* __restrict__ Dp,
    float* __restrict__ yg)
{
    __shared__ float s_dt[SC_T][SC_D];
    __shared__ float s_u [SC_T][SC_D];
    __shared__ float s_z [SC_T][SC_D];
    __shared__ float s_B [SC_T][D_STATE];
    __shared__ float s_C [SC_T][D_STATE];

    const int b  = blockIdx.y;
    const int d0 = blockIdx.x * SC_D;
    const int tid = threadIdx.x;
    const int n  = tid & 15;
    const int dl = tid >> 4;
    const int d  = d0 + dl;

    const float Aval = -__expf(A_log[d*D_STATE + n]);
    const float Dval = Dp[d];
    float s = 0.f;
    const size_t rowbase = (size_t)b * SEQLEN;

    for (int t0 = 0; t0 < SEQLEN; t0 += SC_T) {
        for (int idx = tid; idx < SC_T*SC_D; idx += 512) {
            int tl = idx / SC_D, dd = idx % SC_D;
            size_t r = rowbase + t0 + tl;
            s_dt[tl][dd] = dt[r*D_INNER + d0 + dd];
            s_u [tl][dd] = u [r*D_INNER + d0 + dd];
            s_z [tl][dd] = xz[r*(2*D_INNER) + D_INNER + d0 + dd];
        }
        for (int idx = tid; idx < SC_T*D_STATE; idx += 512) {
            int tl = idx / D_STATE, nn = idx % D_STATE;
            size_t r = rowbase + t0 + tl;
            s_B[tl][nn] = xdbl[r*XD + DT_RANK + nn];
            s_C[tl][nn] = xdbl[r*XD + DT_RANK + D_STATE + nn];
        }
        __syncthreads();

        for (int tl = 0; tl < SC_T; tl++) {
            float dtv = s_dt[tl][dl];
            float uv  = s_u [tl][dl];
            float dA  = __expf(dtv * Aval);
            s = fmaf(dA, s, dtv * uv * s_B[tl][n]);
            float y = s * s_C[tl][n];
#pragma unroll
            for (int off = 8; off; off >>= 1)
                y += __shfl_xor_sync(0xffffffffu, y, off, 16);
            if (n == 0) {
                float zv = s_z[tl][dl];
                float yy = fmaf(Dval, uv, y);
                yg[(rowbase + t0 + tl)*D_INNER + d] = yy * siluf(zv);
            }
        }
        __syncthreads();
    }
}

// ---------------- host ----------------
extern "C" void kernel_launch(void* const* d_in, const int* in_sizes, int n_in,
                              void* d_out, int out_size)
{
    const float* x          = (const float*)d_in[0];
    const float* emb_w      = (const float*)d_in[1];
    const float* emb_b      = (const float*)d_in[2];
    const float* in_proj_w  = (const float*)d_in[3];
    const float* conv_w     = (const float*)d_in[4];
    const float* conv_b     = (const float*)d_in[5];
    const float* x_proj_w   = (const float*)d_in[6];
    const float* dt_proj_w  = (const float*)d_in[7];
    const float* dt_proj_b  = (const float*)d_in[8];
    const float* A_log      = (const float*)d_in[9];
    const float* D_param    = (const float*)d_in[10];
    const float* out_proj_w = (const float*)d_in[11];
    float* out = (float*)d_out;

    float *ph, *pxz, *pu, *pxdbl, *pxpart, *pdt, *pyg;
    cudaGetSymbolAddress((void**)&ph,     g_h);
    cudaGetSymbolAddress((void**)&pxz,    g_xz);
    cudaGetSymbolAddress((void**)&pu,     g_u);
    cudaGetSymbolAddress((void**)&pxdbl,  g_xdbl);
    cudaGetSymbolAddress((void**)&pxpart, g_xdbl_part);
    cudaGetSymbolAddress((void**)&pdt,    g_dt);
    cudaGetSymbolAddress((void**)&pyg,    g_yg);

    embed_k<<<(M_TOK*D_MODEL)/256, 256>>>(x, emb_w, emb_b, ph);

    for (int i = 0; i < NBLK; i++) {
        float* h_out = (i == NBLK-1) ? out : ph;

        // GEMM1: xz = h @ in_proj_w^T   [2048 x 4096 x 1024]
        sgemm_k<128,128,16,8,8,0,false>
            <<<dim3((2*D_INNER)/128, M_TOK/128), 256>>>(
                ph, in_proj_w + (size_t)i*2*D_INNER*D_MODEL, nullptr, pxz,
                M_TOK, 2*D_INNER, D_MODEL, D_MODEL, 0);

        // depthwise conv + silu -> u
        conv_silu_k<<<(M_TOK*D_INNER)/256, 256>>>(
            pxz, conv_w + (size_t)i*D_INNER*D_CONV, conv_b + (size_t)i*D_INNER, pu);

        // GEMM2 (split-K x4): x_dbl partials = u @ x_proj_w^T   [2048 x 96 x 2048]
        sgemm_k<64,96,16,4,6,0,true>
            <<<dim3(1, M_TOK/64, 4), 256>>>(
                pu, x_proj_w + (size_t)i*XD*D_INNER, nullptr, pxpart,
                M_TOK, XD, D_INNER, D_INNER, D_INNER/4);
        reduce4_k<<<(M_TOK*XD + 255)/256, 256>>>(pxdbl, pxpart, M_TOK*XD);

        // GEMM3: dt = softplus(dt_lo @ dt_proj_w^T + b)   [2048 x 2048 x 64], lda=96
        sgemm_k<128,128,16,8,8,1,false>
            <<<dim3(D_INNER/128, M_TOK/128), 256>>>(
                pxdbl, dt_proj_w + (size_t)i*D_INNER*DT_RANK,
                dt_proj_b + (size_t)i*D_INNER, pdt,
                M_TOK, D_INNER, DT_RANK, XD, 0);

        // selective scan + (y + D*u)*silu(z) fused -> yg
        scan_k<<<dim3(D_INNER/SC_D, BATCH), 512>>>(
            pdt, pu, pxdbl, pxz,
            A_log + (size_t)i*D_INNER*D_STATE, D_param + (size_t)i*D_INNER, pyg);

        // GEMM4: h' = silu(yg @ out_proj_w^T)   [2048 x 1024 x 2048]
        sgemm_k<128,128,16,8,8,2,false>
            <<<dim3(D_MODEL/128, M_TOK/128), 256>>>(
                pyg, out_proj_w + (size_t)i*D_MODEL*D_INNER, nullptr, h_out,
                M_TOK, D_MODEL, D_INNER, D_INNER, 0);
    }
    (void)in_sizes; (void)n_in; (void)out_size;
}

// round 12
// speedup vs baseline: 1.9769x; 1.8758x over previous
#include <cuda_runtime.h>
#include <cuda_bf16.h>
#include <math.h>
#include <stdint.h>

#define D_MODEL 1024
#define D_STATE 16
#define D_CONV  4
#define D_INNER 2048
#define DT_RANK 64
#define NBLK    4
#define BATCH   2
#define SEQLEN  1024
#define M_TOK   (BATCH*SEQLEN)   // 2048 tokens
#define XD      96               // dt_rank + 2*d_state

// ---------------- scratch (no allocation allowed) ----------------
__device__ __align__(256) float g_h[M_TOK*D_MODEL];
__device__ __align__(256) float g_xz[(size_t)M_TOK*2*D_INNER];
__device__ __align__(256) float g_u[(size_t)M_TOK*D_INNER];
__device__ __align__(256) float g_xdbl[M_TOK*XD];
__device__ __align__(256) float g_xdbl_part[4*M_TOK*XD];
__device__ __align__(256) float g_dt[(size_t)M_TOK*D_INNER];
__device__ __align__(256) float g_yg[(size_t)M_TOK*D_INNER];
// bf16 split buffers (hi/lo)
__device__ __align__(256) __nv_bfloat16 g_A0[(size_t)M_TOK*D_INNER];
__device__ __align__(256) __nv_bfloat16 g_A1[(size_t)M_TOK*D_INNER];
__device__ __align__(256) __nv_bfloat16 g_W0[(size_t)2*D_INNER*D_MODEL];
__device__ __align__(256) __nv_bfloat16 g_W1[(size_t)2*D_INNER*D_MODEL];

__device__ __forceinline__ float siluf(float v) {
    return v / (1.f + __expf(-v));
}

__device__ __forceinline__ uint32_t smem_u32(const void* p) {
    uint32_t a;
    asm("{ .reg .u64 t; cvta.to.shared.u64 t, %1; cvt.u32.u64 %0, t; }" : "=r"(a) : "l"(p));
    return a;
}
#define SWZ128(o) ((o) ^ (((o) >> 3) & 0x70))

// ---- cp.async helpers (sm_80+ baseline PTX) ----
__device__ __forceinline__ void cp16(uint32_t saddr, const void* gaddr) {
    asm volatile("cp.async.cg.shared.global [%0], [%1], 16;" :: "r"(saddr), "l"(gaddr));
}
__device__ __forceinline__ void cp_commit() { asm volatile("cp.async.commit_group;"); }
template<int N> __device__ __forceinline__ void cp_wait() {
    asm volatile("cp.async.wait_group %0;" :: "n"(N));
}

// ---- ldmatrix + mma.sync (baseline PTX) ----
__device__ __forceinline__ void ldm_x4(uint32_t addr, uint32_t f[4]) {
    asm volatile("ldmatrix.sync.aligned.m8n8.x4.shared.b16 {%0,%1,%2,%3}, [%4];"
                 : "=r"(f[0]), "=r"(f[1]), "=r"(f[2]), "=r"(f[3]) : "r"(addr));
}
__device__ __forceinline__ void mma16816(float c[4], const uint32_t a[4],
                                         uint32_t b0, uint32_t b1) {
    asm volatile(
        "mma.sync.aligned.m16n8k16.row.col.f32.bf16.bf16.f32 "
        "{%0,%1,%2,%3}, {%4,%5,%6,%7}, {%8,%9}, {%0,%1,%2,%3};"
        : "+f"(c[0]), "+f"(c[1]), "+f"(c[2]), "+f"(c[3])
        : "r"(a[0]), "r"(a[1]), "r"(a[2]), "r"(a[3]), "r"(b0), "r"(b1));
}

// ================= bf16x2-split HMMA GEMM =================
//  C[M,N] = (A0+A1)[M,K] * (W0+W1)[N,K]^T, 3-term split, fp32 accum.
//  BM=BN=128, BK=64, 256 threads (8 warps: 4M x 2N), 2-stage cp.async pipeline.
//  EPI: 0 none, 1 softplus(x+bias[n]), 2 silu
#define GSM_STAGE 65536            // 4 sub-tiles x 128x64 bf16 (16KB each)
#define GSM_TOTAL (2*GSM_STAGE)

template<int EPI>
__global__ void __launch_bounds__(256, 1) mmagemm_k(
    const __nv_bfloat16* __restrict__ A0, const __nv_bfloat16* __restrict__ A1,
    const __nv_bfloat16* __restrict__ W0, const __nv_bfloat16* __restrict__ W1,
    const float* __restrict__ bias, float* __restrict__ C,
    int M, int N, int K)
{
    extern __shared__ char dsm[];
    const uint32_t sb = smem_u32(dsm);
    const int tid  = threadIdx.x;
    const int wid  = tid >> 5;
    const int lane = tid & 31;
    const int wm = wid & 3;          // 0..3  (M warps)
    const int wn = wid >> 2;         // 0..1  (N warps)
    const int bm = blockIdx.y * 128;
    const int bn = blockIdx.x * 128;

    const __nv_bfloat16* gb[4] = {
        A0 + (size_t)bm * K, A1 + (size_t)bm * K,
        W0 + (size_t)bn * K, W1 + (size_t)bn * K };

    const int ch = tid & 7;          // 16B chunk in 128B row
    const int r0 = tid >> 3;         // 0..31

    auto issue_chunk = [&](int kt, int stage) {
        uint32_t st = sb + stage * GSM_STAGE;
#pragma unroll
        for (int buf = 0; buf < 4; buf++) {
            const __nv_bfloat16* g = gb[buf] + kt + ch * 8;
#pragma unroll
            for (int j = 0; j < 4; j++) {
                int row = r0 + j * 32;
                uint32_t o = (uint32_t)(row * 128 + ch * 16);
                cp16(st + buf * 16384 + SWZ128(o), g + (size_t)row * K);
            }
        }
    };

    float acc[2][8][4];
#pragma unroll
    for (int i = 0; i < 2; i++)
#pragma unroll
        for (int j = 0; j < 8; j++)
#pragma unroll
            for (int q = 0; q < 4; q++) acc[i][j][q] = 0.f;

    // lane-dependent parts of ldmatrix addressing
    const int a_row = lane & 15;            // + m0
    const int a_kof = (lane >> 4) << 3;     // + k0
    const int b_row = (lane & 7) + ((lane & 16) ? 8 : 0);   // + n0
    const int b_kof = (lane & 8) ? 8 : 0;                   // + k0

    const int T = K / 64;
    issue_chunk(0, 0);
    cp_commit();

    for (int t = 0; t < T; t++) {
        const int s = t & 1;
        if (t + 1 < T) { issue_chunk((t + 1) * 64, s ^ 1); cp_commit(); cp_wait<1>(); }
        else           { cp_wait<0>(); }
        __syncthreads();

        const uint32_t stA0 = sb + s * GSM_STAGE;
        const uint32_t stA1 = stA0 + 16384;
        const uint32_t stW0 = stA0 + 32768;
        const uint32_t stW1 = stA0 + 49152;

#pragma unroll
        for (int kk = 0; kk < 4; kk++) {
            const int k0 = kk * 16;
            uint32_t a0f[2][4], a1f[2][4];
#pragma unroll
            for (int mt = 0; mt < 2; mt++) {
                int row = wm * 32 + mt * 16 + a_row;
                uint32_t o = (uint32_t)(row * 128 + (k0 + a_kof) * 2);
                ldm_x4(stA0 + SWZ128(o), a0f[mt]);
                ldm_x4(stA1 + SWZ128(o), a1f[mt]);
            }
#pragma unroll
            for (int nq = 0; nq < 4; nq++) {
                int nrow = wn * 64 + nq * 16 + b_row;
                uint32_t o = (uint32_t)(nrow * 128 + (k0 + b_kof) * 2);
                uint32_t w0f[4], w1f[4];
                ldm_x4(stW0 + SWZ128(o), w0f);
                ldm_x4(stW1 + SWZ128(o), w1f);
#pragma unroll
                for (int mt = 0; mt < 2; mt++)
#pragma unroll
                    for (int h = 0; h < 2; h++) {
                        float* c = acc[mt][nq * 2 + h];
                        mma16816(c, a0f[mt], w0f[2*h], w0f[2*h+1]);
                        mma16816(c, a0f[mt], w1f[2*h], w1f[2*h+1]);
                        mma16816(c, a1f[mt], w0f[2*h], w0f[2*h+1]);
                    }
            }
        }
        __syncthreads();
    }

    // ---- epilogue ----
    const int erow = lane >> 2;        // 0..7
    const int ecol = (lane & 3) * 2;
#pragma unroll
    for (int mt = 0; mt < 2; mt++) {
#pragma unroll
        for (int nt = 0; nt < 8; nt++) {
            int n = bn + wn * 64 + nt * 8 + ecol;
#pragma unroll
            for (int h = 0; h < 2; h++) {   // h=0: c0,c1 (row), h=1: c2,c3 (row+8)
                int m = bm + wm * 32 + mt * 16 + erow + h * 8;
                float vx = acc[mt][nt][2*h], vy = acc[mt][nt][2*h+1];
                if (EPI == 1) {
                    vx += bias[n]; vy += bias[n+1];
                    vx = fmaxf(vx, 0.f) + log1pf(__expf(-fabsf(vx)));
                    vy = fmaxf(vy, 0.f) + log1pf(__expf(-fabsf(vy)));
                }
                if (EPI == 2) { vx = siluf(vx); vy = siluf(vy); }
                float2 v = {vx, vy};
                *reinterpret_cast<float2*>(C + (size_t)m * N + n) = v;
            }
        }
    }
}

// ================= fp32 -> bf16 hi/lo split =================
__global__ void cvt_split_k(const float* __restrict__ src,
                            __nv_bfloat16* __restrict__ hi,
                            __nv_bfloat16* __restrict__ lo, int n)
{
    int i = blockIdx.x * blockDim.x + threadIdx.x;
    if (i < n) {
        float x = src[i];
        __nv_bfloat16 h = __float2bfloat16(x);
        float r = x - __bfloat162float(h);
        hi[i] = h;
        lo[i] = __float2bfloat16(r);
    }
}
__global__ void cvt_split_strided_k(const float* __restrict__ src, int ld, int cols,
                                    __nv_bfloat16* __restrict__ hi,
                                    __nv_bfloat16* __restrict__ lo, int n)
{
    int i = blockIdx.x * blockDim.x + threadIdx.x;
    if (i < n) {
        int r = i / cols, c = i - r * cols;
        float x = src[(size_t)r * ld + c];
        __nv_bfloat16 h = __float2bfloat16(x);
        float rr = x - __bfloat162float(h);
        hi[i] = h;
        lo[i] = __float2bfloat16(rr);
    }
}

// ================= scalar SGEMM (GEMM2, N=96, split-K) =================
template<int BM,int BN,int BK,int TM,int TN,bool SPLIT>
__global__ void __launch_bounds__((BM/TM)*(BN/TN), 2) sgemm_k(
    const float* __restrict__ A, const float* __restrict__ W,
    float* __restrict__ C, int M, int N, int K, int lda, int ksplit)
{
    constexpr int THREADS = (BM/TM)*(BN/TN);
    __shared__ float As[BK][BM];
    __shared__ float Bs[BK][BN];

    const int bm = blockIdx.y * BM;
    const int bn = blockIdx.x * BN;
    int k0 = 0, kend = K;
    if (SPLIT) {
        k0 = blockIdx.z * ksplit;
        kend = k0 + ksplit;
        C += (size_t)blockIdx.z * (size_t)M * N;
    }
    const int tid = threadIdx.x;
    const int tx = tid % (BN/TN);
    const int ty = tid / (BN/TN);

    float acc[TM][TN];
#pragma unroll
    for (int i = 0; i < TM; i++)
#pragma unroll
        for (int j = 0; j < TN; j++) acc[i][j] = 0.f;

    for (int kt = k0; kt < kend; kt += BK) {
#pragma unroll
        for (int idx = tid; idx < BM*(BK/4); idx += THREADS) {
            int row = idx / (BK/4), kq = idx % (BK/4);
            float4 v = *reinterpret_cast<const float4*>(A + (size_t)(bm+row)*lda + kt + kq*4);
            As[kq*4+0][row] = v.x; As[kq*4+1][row] = v.y;
            As[kq*4+2][row] = v.z; As[kq*4+3][row] = v.w;
        }
#pragma unroll
        for (int idx = tid; idx < BN*(BK/4); idx += THREADS) {
            int col = idx / (BK/4), kq = idx % (BK/4);
            float4 v = *reinterpret_cast<const float4*>(W + (size_t)(bn+col)*K + kt + kq*4);
            Bs[kq*4+0][col] = v.x; Bs[kq*4+1][col] = v.y;
            Bs[kq*4+2][col] = v.z; Bs[kq*4+3][col] = v.w;
        }
        __syncthreads();
#pragma unroll
        for (int k = 0; k < BK; k++) {
            float a[TM], b[TN];
#pragma unroll
            for (int i = 0; i < TM; i++) a[i] = As[k][ty*TM + i];
#pragma unroll
            for (int j = 0; j < TN; j++) b[j] = Bs[k][tx*TN + j];
#pragma unroll
            for (int i = 0; i < TM; i++)
#pragma unroll
                for (int j = 0; j < TN; j++)
                    acc[i][j] = fmaf(a[i], b[j], acc[i][j]);
        }
        __syncthreads();
    }
#pragma unroll
    for (int i = 0; i < TM; i++) {
        int m = bm + ty*TM + i;
#pragma unroll
        for (int j = 0; j < TN; j++)
            C[(size_t)m * N + bn + tx*TN + j] = acc[i][j];
    }
}

// ---------------- embedding ----------------
__global__ void embed_k(const float* __restrict__ x, const float* __restrict__ ew,
                        const float* __restrict__ eb, float* __restrict__ h)
{
    int i = blockIdx.x * blockDim.x + threadIdx.x;
    int d = i % D_MODEL, m = i / D_MODEL;
    h[i] = fmaf(x[m], ew[d], eb[d]);
}

// ---------------- causal depthwise conv (width 4) + silu ----------------
__global__ void conv_silu_k(const float* __restrict__ xz, const float* __restrict__ cw,
                            const float* __restrict__ cb, float* __restrict__ u)
{
    int i = blockIdx.x * blockDim.x + threadIdx.x;
    int d = i % D_INNER;
    int m = i / D_INNER;
    int t = m % SEQLEN;
    float acc = cb[d];
#pragma unroll
    for (int k = 0; k < D_CONV; k++) {
        int tt = t - (D_CONV-1) + k;
        if (tt >= 0)
            acc = fmaf(cw[d*D_CONV + k], xz[(size_t)(m-(D_CONV-1)+k)*(2*D_INNER) + d], acc);
    }
    u[i] = siluf(acc);
}

// ---------------- reduce split-K partials ----------------
__global__ void reduce4_k(float* __restrict__ out, const float* __restrict__ part, int n)
{
    int i = blockIdx.x * blockDim.x + threadIdx.x;
    if (i < n)
        out[i] = (part[i] + part[n + i]) + (part[2*n + i] + part[3*n + i]);
}

// ---------------- selective scan + gating fused ----------------
#define SC_D 32
#define SC_T 64
__global__ void __launch_bounds__(512) scan_k(
    const float* __restrict__ dt, const float* __restrict__ u,
    const float* __restrict__ xdbl, const float* __restrict__ xz,
    const float* __restrict__ A_log, const float* __restrict__ Dp,
    float* __restrict__ yg)
{
    __shared__ float s_dt[SC_T][SC_D];
    __shared__ float s_u [SC_T][SC_D];
    __shared__ float s_z [SC_T][SC_D];
    __shared__ float s_B [SC_T][D_STATE];
    __shared__ float s_C [SC_T][D_STATE];

    const int b  = blockIdx.y;
    const int d0 = blockIdx.x * SC_D;
    const int tid = threadIdx.x;
    const int n  = tid & 15;
    const int dl = tid >> 4;
    const int d  = d0 + dl;

    const float Aval = -__expf(A_log[d*D_STATE + n]);
    const float Dval = Dp[d];
    float s = 0.f;
    const size_t rowbase = (size_t)b * SEQLEN;

    for (int t0 = 0; t0 < SEQLEN; t0 += SC_T) {
        for (int idx = tid; idx < SC_T*SC_D; idx += 512) {
            int tl = idx / SC_D, dd = idx % SC_D;
            size_t r = rowbase + t0 + tl;
            s_dt[tl][dd] = dt[r*D_INNER + d0 + dd];
            s_u [tl][dd] = u [r*D_INNER + d0 + dd];
            s_z [tl][dd] = xz[r*(2*D_INNER) + D_INNER + d0 + dd];
        }
        for (int idx = tid; idx < SC_T*D_STATE; idx += 512) {
            int tl = idx / D_STATE, nn = idx % D_STATE;
            size_t r = rowbase + t0 + tl;
            s_B[tl][nn] = xdbl[r*XD + DT_RANK + nn];
            s_C[tl][nn] = xdbl[r*XD + DT_RANK + D_STATE + nn];
        }
        __syncthreads();

        for (int tl = 0; tl < SC_T; tl++) {
            float dtv = s_dt[tl][dl];
            float uv  = s_u [tl][dl];
            float dA  = __expf(dtv * Aval);
            s = fmaf(dA, s, dtv * uv * s_B[tl][n]);
            float y = s * s_C[tl][n];
#pragma unroll
            for (int off = 8; off; off >>= 1)
                y += __shfl_xor_sync(0xffffffffu, y, off, 16);
            if (n == 0) {
                float zv = s_z[tl][dl];
                float yy = fmaf(Dval, uv, y);
                yg[(rowbase + t0 + tl)*D_INNER + d] = yy * siluf(zv);
            }
        }
        __syncthreads();
    }
}

// ---------------- host ----------------
extern "C" void kernel_launch(void* const* d_in, const int* in_sizes, int n_in,
                              void* d_out, int out_size)
{
    const float* x          = (const float*)d_in[0];
    const float* emb_w      = (const float*)d_in[1];
    const float* emb_b      = (const float*)d_in[2];
    const float* in_proj_w  = (const float*)d_in[3];
    const float* conv_w     = (const float*)d_in[4];
    const float* conv_b     = (const float*)d_in[5];
    const float* x_proj_w   = (const float*)d_in[6];
    const float* dt_proj_w  = (const float*)d_in[7];
    const float* dt_proj_b  = (const float*)d_in[8];
    const float* A_log      = (const float*)d_in[9];
    const float* D_param    = (const float*)d_in[10];
    const float* out_proj_w = (const float*)d_in[11];
    float* out = (float*)d_out;

    float *ph, *pxz, *pu, *pxdbl, *pxpart, *pdt, *pyg;
    __nv_bfloat16 *pA0, *pA1, *pW0, *pW1;
    cudaGetSymbolAddress((void**)&ph,     g_h);
    cudaGetSymbolAddress((void**)&pxz,    g_xz);
    cudaGetSymbolAddress((void**)&pu,     g_u);
    cudaGetSymbolAddress((void**)&pxdbl,  g_xdbl);
    cudaGetSymbolAddress((void**)&pxpart, g_xdbl_part);
    cudaGetSymbolAddress((void**)&pdt,    g_dt);
    cudaGetSymbolAddress((void**)&pyg,    g_yg);
    cudaGetSymbolAddress((void**)&pA0,    g_A0);
    cudaGetSymbolAddress((void**)&pA1,    g_A1);
    cudaGetSymbolAddress((void**)&pW0,    g_W0);
    cudaGetSymbolAddress((void**)&pW1,    g_W1);

    cudaFuncSetAttribute(mmagemm_k<0>, cudaFuncAttributeMaxDynamicSharedMemorySize, GSM_TOTAL);
    cudaFuncSetAttribute(mmagemm_k<1>, cudaFuncAttributeMaxDynamicSharedMemorySize, GSM_TOTAL);
    cudaFuncSetAttribute(mmagemm_k<2>, cudaFuncAttributeMaxDynamicSharedMemorySize, GSM_TOTAL);

    embed_k<<<(M_TOK*D_MODEL)/256, 256>>>(x, emb_w, emb_b, ph);

    for (int i = 0; i < NBLK; i++) {
        float* h_out = (i == NBLK-1) ? out : ph;

        // --- GEMM1 (HMMA): xz = h @ in_proj_w^T  [2048 x 4096 x 1024]
        cvt_split_k<<<(M_TOK*D_MODEL)/256, 256>>>(ph, pA0, pA1, M_TOK*D_MODEL);
        cvt_split_k<<<(2*D_INNER*D_MODEL)/256, 256>>>(
            in_proj_w + (size_t)i*2*D_INNER*D_MODEL, pW0, pW1, 2*D_INNER*D_MODEL);
        mmagemm_k<0><<<dim3((2*D_INNER)/128, M_TOK/128), 256, GSM_TOTAL>>>(
            pA0, pA1, pW0, pW1, nullptr, pxz, M_TOK, 2*D_INNER, D_MODEL);

        // --- depthwise conv + silu -> u
        conv_silu_k<<<(M_TOK*D_INNER)/256, 256>>>(
            pxz, conv_w + (size_t)i*D_INNER*D_CONV, conv_b + (size_t)i*D_INNER, pu);

        // --- GEMM2 (scalar split-K x4): x_dbl = u @ x_proj_w^T  [2048 x 96 x 2048]
        sgemm_k<64,96,16,4,6,true>
            <<<dim3(1, M_TOK/64, 4), 256>>>(
                pu, x_proj_w + (size_t)i*XD*D_INNER, pxpart,
                M_TOK, XD, D_INNER, D_INNER, D_INNER/4);
        reduce4_k<<<(M_TOK*XD + 255)/256, 256>>>(pxdbl, pxpart, M_TOK*XD);

        // --- GEMM3 (HMMA): dt = softplus(dt_lo @ dt_proj_w^T + b)  [2048 x 2048 x 64]
        cvt_split_strided_k<<<(M_TOK*DT_RANK)/256, 256>>>(
            pxdbl, XD, DT_RANK, pA0, pA1, M_TOK*DT_RANK);
        cvt_split_k<<<(D_INNER*DT_RANK)/256, 256>>>(
            dt_proj_w + (size_t)i*D_INNER*DT_RANK, pW0, pW1, D_INNER*DT_RANK);
        mmagemm_k<1><<<dim3(D_INNER/128, M_TOK/128), 256, GSM_TOTAL>>>(
            pA0, pA1, pW0, pW1, dt_proj_b + (size_t)i*D_INNER, pdt,
            M_TOK, D_INNER, DT_RANK);

        // --- selective scan + gating
        scan_k<<<dim3(D_INNER/SC_D, BATCH), 512>>>(
            pdt, pu, pxdbl, pxz,
            A_log + (size_t)i*D_INNER*D_STATE, D_param + (size_t)i*D_INNER, pyg);

        // --- GEMM4 (HMMA): h' = silu(yg @ out_proj_w^T)  [2048 x 1024 x 2048]
        cvt_split_k<<<(M_TOK*D_INNER)/256, 256>>>(pyg, pA0, pA1, M_TOK*D_INNER);
        cvt_split_k<<<(D_MODEL*D_INNER)/256, 256>>>(
            out_proj_w + (size_t)i*D_MODEL*D_INNER, pW0, pW1, D_MODEL*D_INNER);
        mmagemm_k<2><<<dim3(D_MODEL/128, M_TOK/128), 256, GSM_TOTAL>>>(
            pA0, pA1, pW0, pW1, nullptr, h_out, M_TOK, D_MODEL, D_INNER);
    }
    (void)in_sizes; (void)n_in; (void)out_size;
}

// round 13
// speedup vs baseline: 2.0032x; 1.0133x over previous
#include <cuda_runtime.h>
#include <cuda_bf16.h>
#include <math.h>
#include <stdint.h>

#define D_MODEL 1024
#define D_STATE 16
#define D_CONV  4
#define D_INNER 2048
#define DT_RANK 64
#define NBLK    4
#define BATCH   2
#define SEQLEN  1024
#define M_TOK   (BATCH*SEQLEN)   // 2048 tokens
#define XD      96               // dt_rank + 2*d_state

// ---------------- scratch (no allocation allowed) ----------------
__device__ __align__(256) float g_xz[(size_t)M_TOK*2*D_INNER];
__device__ __align__(256) float g_u[(size_t)M_TOK*D_INNER];
__device__ __align__(256) float g_xdbl[M_TOK*XD];
__device__ __align__(256) float g_part[(size_t)8*M_TOK*128];
__device__ __align__(256) float g_dt[(size_t)M_TOK*D_INNER];
// bf16 split activation buffers (hi/lo): A = generic (u / dt_lo / yg), H = hidden state
__device__ __align__(256) __nv_bfloat16 g_A0[(size_t)M_TOK*D_INNER];
__device__ __align__(256) __nv_bfloat16 g_A1[(size_t)M_TOK*D_INNER];
__device__ __align__(256) __nv_bfloat16 g_H0[(size_t)M_TOK*D_MODEL];
__device__ __align__(256) __nv_bfloat16 g_H1[(size_t)M_TOK*D_MODEL];
// bf16 split weight buffers
__device__ __align__(256) __nv_bfloat16 g_W0[(size_t)2*D_INNER*D_MODEL];
__device__ __align__(256) __nv_bfloat16 g_W1[(size_t)2*D_INNER*D_MODEL];

__device__ __forceinline__ float siluf(float v) {
    return v / (1.f + __expf(-v));
}

__device__ __forceinline__ uint32_t smem_u32(const void* p) {
    uint32_t a;
    asm("{ .reg .u64 t; cvta.to.shared.u64 t, %1; cvt.u32.u64 %0, t; }" : "=r"(a) : "l"(p));
    return a;
}
#define SWZ128(o) ((o) ^ (((o) >> 3) & 0x70))

// ---- cp.async helpers ----
__device__ __forceinline__ void cp16(uint32_t saddr, const void* gaddr) {
    asm volatile("cp.async.cg.shared.global [%0], [%1], 16;" :: "r"(saddr), "l"(gaddr));
}
__device__ __forceinline__ void cp_commit() { asm volatile("cp.async.commit_group;"); }
template<int N> __device__ __forceinline__ void cp_wait() {
    asm volatile("cp.async.wait_group %0;" :: "n"(N));
}

// ---- ldmatrix + mma.sync ----
__device__ __forceinline__ void ldm_x4(uint32_t addr, uint32_t f[4]) {
    asm volatile("ldmatrix.sync.aligned.m8n8.x4.shared.b16 {%0,%1,%2,%3}, [%4];"
                 : "=r"(f[0]), "=r"(f[1]), "=r"(f[2]), "=r"(f[3]) : "r"(addr));
}
__device__ __forceinline__ void mma16816(float c[4], const uint32_t a[4],
                                         uint32_t b0, uint32_t b1) {
    asm volatile(
        "mma.sync.aligned.m16n8k16.row.col.f32.bf16.bf16.f32 "
        "{%0,%1,%2,%3}, {%4,%5,%6,%7}, {%8,%9}, {%0,%1,%2,%3};"
        : "+f"(c[0]), "+f"(c[1]), "+f"(c[2]), "+f"(c[3])
        : "r"(a[0]), "r"(a[1]), "r"(a[2]), "r"(a[3]), "r"(b0), "r"(b1));
}

// ================= bf16x2-split HMMA GEMM =================
//  C[M,N] = (A0+A1)[M,K] * (W0+W1)[N,K]^T, 3-term split, fp32 accum.
//  BM=BN=128, BK=64, 256 threads (8 warps: 4M x 2N), 3-stage cp.async pipeline.
//  EPI: 0 none, 1 softplus(x+bias[n]), 2 silu
//  OSPLIT: write hi/lo bf16 outputs instead of fp32
//  SPLITK: grid.z K-splits of size ksplit, fp32 partials at z*M*N
#define GSM_STAGE 65536            // 4 sub-tiles x 128x64 bf16 (16KB each)
#define GSM_TOTAL (3*GSM_STAGE)

template<int EPI, int OSPLIT, int SPLITK>
__global__ void __launch_bounds__(256, 1) mmagemm_k(
    const __nv_bfloat16* __restrict__ A0, const __nv_bfloat16* __restrict__ A1,
    const __nv_bfloat16* __restrict__ W0, const __nv_bfloat16* __restrict__ W1,
    const float* __restrict__ bias, float* __restrict__ C,
    __nv_bfloat16* __restrict__ Chi, __nv_bfloat16* __restrict__ Clo,
    int M, int N, int K, int ksplit)
{
    extern __shared__ char dsm[];
    const uint32_t sb = smem_u32(dsm);
    const int tid  = threadIdx.x;
    const int wid  = tid >> 5;
    const int lane = tid & 31;
    const int wm = wid & 3;
    const int wn = wid >> 2;
    const int bm = blockIdx.y * 128;
    const int bn = blockIdx.x * 128;

    int kbase = 0, Kloc = K;
    if (SPLITK) {
        kbase = blockIdx.z * ksplit;
        Kloc  = ksplit;
        C += (size_t)blockIdx.z * (size_t)M * N;
    }

    const __nv_bfloat16* gb[4] = {
        A0 + (size_t)bm * K + kbase, A1 + (size_t)bm * K + kbase,
        W0 + (size_t)bn * K + kbase, W1 + (size_t)bn * K + kbase };

    const int ch = tid & 7;          // 16B chunk in 128B row
    const int r0 = tid >> 3;         // 0..31

    auto issue_chunk = [&](int kt, int stage) {
        uint32_t st = sb + stage * GSM_STAGE;
#pragma unroll
        for (int buf = 0; buf < 4; buf++) {
            const __nv_bfloat16* g = gb[buf] + kt + ch * 8;
#pragma unroll
            for (int j = 0; j < 4; j++) {
                int row = r0 + j * 32;
                uint32_t o = (uint32_t)(row * 128 + ch * 16);
                cp16(st + buf * 16384 + SWZ128(o), g + (size_t)row * K);
            }
        }
    };

    float acc[2][8][4];
#pragma unroll
    for (int i = 0; i < 2; i++)
#pragma unroll
        for (int j = 0; j < 8; j++)
#pragma unroll
            for (int q = 0; q < 4; q++) acc[i][j][q] = 0.f;

    const int a_row = lane & 15;
    const int a_kof = (lane >> 4) << 3;
    const int b_row = (lane & 7) + ((lane & 16) ? 8 : 0);
    const int b_kof = (lane & 8) ? 8 : 0;

    const int T = Kloc / 64;
    issue_chunk(0, 0);
    cp_commit();
    if (T > 1) issue_chunk(64, 1);
    cp_commit();                          // always commit (possibly empty)

    for (int t = 0; t < T; t++) {
        const int s = t % 3;
        __syncthreads();                  // all warps done reading stage (t+2)%3
        if (t + 2 < T) issue_chunk((t + 2) * 64, (t + 2) % 3);
        cp_commit();                      // always commit to keep group count exact
        cp_wait<2>();                     // chunks <= t complete
        __syncthreads();

        const uint32_t stA0 = sb + s * GSM_STAGE;
        const uint32_t stA1 = stA0 + 16384;
        const uint32_t stW0 = stA0 + 32768;
        const uint32_t stW1 = stA0 + 49152;

#pragma unroll
        for (int kk = 0; kk < 4; kk++) {
            const int k0 = kk * 16;
            uint32_t a0f[2][4], a1f[2][4];
#pragma unroll
            for (int mt = 0; mt < 2; mt++) {
                int row = wm * 32 + mt * 16 + a_row;
                uint32_t o = (uint32_t)(row * 128 + (k0 + a_kof) * 2);
                ldm_x4(stA0 + SWZ128(o), a0f[mt]);
                ldm_x4(stA1 + SWZ128(o), a1f[mt]);
            }
#pragma unroll
            for (int nq = 0; nq < 4; nq++) {
                int nrow = wn * 64 + nq * 16 + b_row;
                uint32_t o = (uint32_t)(nrow * 128 + (k0 + b_kof) * 2);
                uint32_t w0f[4], w1f[4];
                ldm_x4(stW0 + SWZ128(o), w0f);
                ldm_x4(stW1 + SWZ128(o), w1f);
#pragma unroll
                for (int mt = 0; mt < 2; mt++)
#pragma unroll
                    for (int h = 0; h < 2; h++) {
                        float* c = acc[mt][nq * 2 + h];
                        mma16816(c, a0f[mt], w0f[2*h], w0f[2*h+1]);
                        mma16816(c, a0f[mt], w1f[2*h], w1f[2*h+1]);
                        mma16816(c, a1f[mt], w0f[2*h], w0f[2*h+1]);
                    }
            }
        }
    }

    // ---- epilogue ----
    const int erow = lane >> 2;
    const int ecol = (lane & 3) * 2;
#pragma unroll
    for (int mt = 0; mt < 2; mt++) {
#pragma unroll
        for (int nt = 0; nt < 8; nt++) {
            int n = bn + wn * 64 + nt * 8 + ecol;
#pragma unroll
            for (int h = 0; h < 2; h++) {
                int m = bm + wm * 32 + mt * 16 + erow + h * 8;
                float vx = acc[mt][nt][2*h], vy = acc[mt][nt][2*h+1];
                if (EPI == 1) {
                    vx += bias[n]; vy += bias[n+1];
                    vx = fmaxf(vx, 0.f) + log1pf(__expf(-fabsf(vx)));
                    vy = fmaxf(vy, 0.f) + log1pf(__expf(-fabsf(vy)));
                }
                if (EPI == 2) { vx = siluf(vx); vy = siluf(vy); }
                if (OSPLIT) {
                    __nv_bfloat16 hx = __float2bfloat16(vx);
                    __nv_bfloat16 hy = __float2bfloat16(vy);
                    __nv_bfloat162 hp; hp.x = hx; hp.y = hy;
                    __nv_bfloat162 lp;
                    lp.x = __float2bfloat16(vx - __bfloat162float(hx));
                    lp.y = __float2bfloat16(vy - __bfloat162float(hy));
                    *reinterpret_cast<__nv_bfloat162*>(Chi + (size_t)m * N + n) = hp;
                    *reinterpret_cast<__nv_bfloat162*>(Clo + (size_t)m * N + n) = lp;
                } else {
                    float2 v = {vx, vy};
                    *reinterpret_cast<float2*>(C + (size_t)m * N + n) = v;
                }
            }
        }
    }
}

// ================= fp32 -> bf16 hi/lo split (weights) =================
__global__ void cvt_split_k(const float* __restrict__ src,
                            __nv_bfloat16* __restrict__ hi,
                            __nv_bfloat16* __restrict__ lo, int n)
{
    int i = blockIdx.x * blockDim.x + threadIdx.x;
    if (i < n) {
        float x = src[i];
        __nv_bfloat16 h = __float2bfloat16(x);
        hi[i] = h;
        lo[i] = __float2bfloat16(x - __bfloat162float(h));
    }
}
// x_proj weights padded from 96 to 128 rows (zeros)
__global__ void cvt_pad_k(const float* __restrict__ src,
                          __nv_bfloat16* __restrict__ hi,
                          __nv_bfloat16* __restrict__ lo)
{
    int i = blockIdx.x * blockDim.x + threadIdx.x;   // 128*D_INNER
    int r = i / D_INNER;
    float x = (r < XD) ? src[i - (size_t)0 + 0] : 0.f;   // src layout [96][D_INNER], same linear index while r<96
    if (r < XD) x = src[i];
    __nv_bfloat16 h = __float2bfloat16(x);
    hi[i] = h;
    lo[i] = __float2bfloat16(x - __bfloat162float(h));
}

// ================= embedding (writes split directly) =================
__global__ void embed_split_k(const float* __restrict__ x, const float* __restrict__ ew,
                              const float* __restrict__ eb,
                              __nv_bfloat16* __restrict__ hi,
                              __nv_bfloat16* __restrict__ lo)
{
    int i = blockIdx.x * blockDim.x + threadIdx.x;
    int d = i % D_MODEL, m = i / D_MODEL;
    float v = fmaf(x[m], ew[d], eb[d]);
    __nv_bfloat16 h = __float2bfloat16(v);
    hi[i] = h;
    lo[i] = __float2bfloat16(v - __bfloat162float(h));
}

// ============ causal depthwise conv + silu (fp32 + split outputs) ============
__global__ void conv_silu_k(const float* __restrict__ xz, const float* __restrict__ cw,
                            const float* __restrict__ cb, float* __restrict__ u,
                            __nv_bfloat16* __restrict__ uhi, __nv_bfloat16* __restrict__ ulo)
{
    int i = blockIdx.x * blockDim.x + threadIdx.x;
    int d = i % D_INNER;
    int m = i / D_INNER;
    int t = m % SEQLEN;
    float acc = cb[d];
#pragma unroll
    for (int k = 0; k < D_CONV; k++) {
        int tt = t - (D_CONV-1) + k;
        if (tt >= 0)
            acc = fmaf(cw[d*D_CONV + k], xz[(size_t)(m-(D_CONV-1)+k)*(2*D_INNER) + d], acc);
    }
    float v = siluf(acc);
    u[i] = v;
    __nv_bfloat16 h = __float2bfloat16(v);
    uhi[i] = h;
    ulo[i] = __float2bfloat16(v - __bfloat162float(h));
}

// ======= reduce 8 split-K partials -> xdbl fp32 + dt_lo bf16 split =======
__global__ void reduce8_k(const float* __restrict__ part,
                          float* __restrict__ xdbl,
                          __nv_bfloat16* __restrict__ dh, __nv_bfloat16* __restrict__ dl)
{
    int i = blockIdx.x * blockDim.x + threadIdx.x;   // M_TOK*96
    if (i < M_TOK * XD) {
        int m = i / XD, c = i - m * XD;
        float s = 0.f;
#pragma unroll
        for (int z = 0; z < 8; z++)
            s += part[(size_t)z * M_TOK * 128 + (size_t)m * 128 + c];
        xdbl[i] = s;
        if (c < DT_RANK) {
            __nv_bfloat16 h = __float2bfloat16(s);
            dh[(size_t)m * DT_RANK + c] = h;
            dl[(size_t)m * DT_RANK + c] = __float2bfloat16(s - __bfloat162float(h));
        }
    }
}

// ---------------- selective scan + gating fused (writes yg split) ----------------
#define SC_D 32
#define SC_T 64
__global__ void __launch_bounds__(512) scan_k(
    const float* __restrict__ dt, const float* __restrict__ u,
    const float* __restrict__ xdbl, const float* __restrict__ xz,
    const float* __restrict__ A_log, const float* __restrict__ Dp,
    __nv_bfloat16* __restrict__ yhi, __nv_bfloat16* __restrict__ ylo)
{
    __shared__ float s_dt[SC_T][SC_D];
    __shared__ float s_u [SC_T][SC_D];
    __shared__ float s_z [SC_T][SC_D];
    __shared__ float s_B [SC_T][D_STATE];
    __shared__ float s_C [SC_T][D_STATE];

    const int b  = blockIdx.y;
    const int d0 = blockIdx.x * SC_D;
    const int tid = threadIdx.x;
    const int n  = tid & 15;
    const int dl = tid >> 4;
    const int d  = d0 + dl;

    const float Aval = -__expf(A_log[d*D_STATE + n]);
    const float Dval = Dp[d];
    float s = 0.f;
    const size_t rowbase = (size_t)b * SEQLEN;

    for (int t0 = 0; t0 < SEQLEN; t0 += SC_T) {
        for (int idx = tid; idx < SC_T*SC_D; idx += 512) {
            int tl = idx / SC_D, dd = idx % SC_D;
            size_t r = rowbase + t0 + tl;
            s_dt[tl][dd] = dt[r*D_INNER + d0 + dd];
            s_u [tl][dd] = u [r*D_INNER + d0 + dd];
            s_z [tl][dd] = xz[r*(2*D_INNER) + D_INNER + d0 + dd];
        }
        for (int idx = tid; idx < SC_T*D_STATE; idx += 512) {
            int tl = idx / D_STATE, nn = idx % D_STATE;
            size_t r = rowbase + t0 + tl;
            s_B[tl][nn] = xdbl[r*XD + DT_RANK + nn];
            s_C[tl][nn] = xdbl[r*XD + DT_RANK + D_STATE + nn];
        }
        __syncthreads();

        for (int tl = 0; tl < SC_T; tl++) {
            float dtv = s_dt[tl][dl];
            float uv  = s_u [tl][dl];
            float dA  = __expf(dtv * Aval);
            s = fmaf(dA, s, dtv * uv * s_B[tl][n]);
            float y = s * s_C[tl][n];
#pragma unroll
            for (int off = 8; off; off >>= 1)
                y += __shfl_xor_sync(0xffffffffu, y, off, 16);
            if (n == 0) {
                float zv = s_z[tl][dl];
                float v  = fmaf(Dval, uv, y) * siluf(zv);
                __nv_bfloat16 h = __float2bfloat16(v);
                size_t o = (rowbase + t0 + tl)*D_INNER + d;
                yhi[o] = h;
                ylo[o] = __float2bfloat16(v - __bfloat162float(h));
            }
        }
        __syncthreads();
    }
}

// ---------------- host ----------------
extern "C" void kernel_launch(void* const* d_in, const int* in_sizes, int n_in,
                              void* d_out, int out_size)
{
    const float* x          = (const float*)d_in[0];
    const float* emb_w      = (const float*)d_in[1];
    const float* emb_b      = (const float*)d_in[2];
    const float* in_proj_w  = (const float*)d_in[3];
    const float* conv_w     = (const float*)d_in[4];
    const float* conv_b     = (const float*)d_in[5];
    const float* x_proj_w   = (const float*)d_in[6];
    const float* dt_proj_w  = (const float*)d_in[7];
    const float* dt_proj_b  = (const float*)d_in[8];
    const float* A_log      = (const float*)d_in[9];
    const float* D_param    = (const float*)d_in[10];
    const float* out_proj_w = (const float*)d_in[11];
    float* out = (float*)d_out;

    float *pxz, *pu, *pxdbl, *ppart, *pdt;
    __nv_bfloat16 *pA0, *pA1, *pH0, *pH1, *pW0, *pW1;
    cudaGetSymbolAddress((void**)&pxz,   g_xz);
    cudaGetSymbolAddress((void**)&pu,    g_u);
    cudaGetSymbolAddress((void**)&pxdbl, g_xdbl);
    cudaGetSymbolAddress((void**)&ppart, g_part);
    cudaGetSymbolAddress((void**)&pdt,   g_dt);
    cudaGetSymbolAddress((void**)&pA0,   g_A0);
    cudaGetSymbolAddress((void**)&pA1,   g_A1);
    cudaGetSymbolAddress((void**)&pH0,   g_H0);
    cudaGetSymbolAddress((void**)&pH1,   g_H1);
    cudaGetSymbolAddress((void**)&pW0,   g_W0);
    cudaGetSymbolAddress((void**)&pW1,   g_W1);

    cudaFuncSetAttribute(mmagemm_k<0,0,0>, cudaFuncAttributeMaxDynamicSharedMemorySize, GSM_TOTAL);
    cudaFuncSetAttribute(mmagemm_k<0,0,1>, cudaFuncAttributeMaxDynamicSharedMemorySize, GSM_TOTAL);
    cudaFuncSetAttribute(mmagemm_k<1,0,0>, cudaFuncAttributeMaxDynamicSharedMemorySize, GSM_TOTAL);
    cudaFuncSetAttribute(mmagemm_k<2,1,0>, cudaFuncAttributeMaxDynamicSharedMemorySize, GSM_TOTAL);
    cudaFuncSetAttribute(mmagemm_k<2,0,0>, cudaFuncAttributeMaxDynamicSharedMemorySize, GSM_TOTAL);

    embed_split_k<<<(M_TOK*D_MODEL)/256, 256>>>(x, emb_w, emb_b, pH0, pH1);

    for (int i = 0; i < NBLK; i++) {
        // --- GEMM1 (HMMA): xz = h @ in_proj_w^T  [2048 x 4096 x 1024]
        cvt_split_k<<<(2*D_INNER*D_MODEL)/256, 256>>>(
            in_proj_w + (size_t)i*2*D_INNER*D_MODEL, pW0, pW1, 2*D_INNER*D_MODEL);
        mmagemm_k<0,0,0><<<dim3((2*D_INNER)/128, M_TOK/128), 256, GSM_TOTAL>>>(
            pH0, pH1, pW0, pW1, nullptr, pxz, nullptr, nullptr,
            M_TOK, 2*D_INNER, D_MODEL, 0);

        // --- depthwise conv + silu -> u (fp32 + split)
        conv_silu_k<<<(M_TOK*D_INNER)/256, 256>>>(
            pxz, conv_w + (size_t)i*D_INNER*D_CONV, conv_b + (size_t)i*D_INNER,
            pu, pA0, pA1);

        // --- GEMM2 (HMMA split-K x8): x_dbl = u @ x_proj_w^T  [2048 x 96(pad128) x 2048]
        cvt_pad_k<<<(128*D_INNER)/256, 256>>>(
            x_proj_w + (size_t)i*XD*D_INNER, pW0, pW1);
        mmagemm_k<0,0,1><<<dim3(1, M_TOK/128, 8), 256, GSM_TOTAL>>>(
            pA0, pA1, pW0, pW1, nullptr, ppart, nullptr, nullptr,
            M_TOK, 128, D_INNER, D_INNER/8);
        reduce8_k<<<(M_TOK*XD + 255)/256, 256>>>(ppart, pxdbl, pA0, pA1);

        // --- GEMM3 (HMMA): dt = softplus(dt_lo @ dt_proj_w^T + b)  [2048 x 2048 x 64]
        cvt_split_k<<<(D_INNER*DT_RANK)/256, 256>>>(
            dt_proj_w + (size_t)i*D_INNER*DT_RANK, pW0, pW1, D_INNER*DT_RANK);
        mmagemm_k<1,0,0><<<dim3(D_INNER/128, M_TOK/128), 256, GSM_TOTAL>>>(
            pA0, pA1, pW0, pW1, dt_proj_b + (size_t)i*D_INNER, pdt, nullptr, nullptr,
            M_TOK, D_INNER, DT_RANK, 0);

        // --- selective scan + gating -> yg split
        scan_k<<<dim3(D_INNER/SC_D, BATCH), 512>>>(
            pdt, pu, pxdbl, pxz,
            A_log + (size_t)i*D_INNER*D_STATE, D_param + (size_t)i*D_INNER, pA0, pA1);

        // --- GEMM4 (HMMA): h' = silu(yg @ out_proj_w^T)  [2048 x 1024 x 2048]
        cvt_split_k<<<(D_MODEL*D_INNER)/256, 256>>>(
            out_proj_w + (size_t)i*D_MODEL*D_INNER, pW0, pW1, D_MODEL*D_INNER);
        if (i == NBLK-1) {
            mmagemm_k<2,0,0><<<dim3(D_MODEL/128, M_TOK/128), 256, GSM_TOTAL>>>(
                pA0, pA1, pW0, pW1, nullptr, out, nullptr, nullptr,
                M_TOK, D_MODEL, D_INNER, 0);
        } else {
            mmagemm_k<2,1,0><<<dim3(D_MODEL/128, M_TOK/128), 256, GSM_TOTAL>>>(
                pA0, pA1, pW0, pW1, nullptr, nullptr, pH0, pH1,
                M_TOK, D_MODEL, D_INNER, 0);
        }
    }
    (void)in_sizes; (void)n_in; (void)out_size;
}

// round 14
// speedup vs baseline: 2.0539x; 1.0253x over previous
#include <cuda_runtime.h>
#include <cuda_bf16.h>
#include <math.h>
#include <stdint.h>

#define D_MODEL 1024
#define D_STATE 16
#define D_CONV  4
#define D_INNER 2048
#define DT_RANK 64
#define NBLK    4
#define BATCH   2
#define SEQLEN  1024
#define M_TOK   (BATCH*SEQLEN)   // 2048 tokens
#define XD      96               // dt_rank + 2*d_state

// weight layout inside the big split buffers (elems, per layer)
#define WL_IN   (2*D_INNER*D_MODEL)   // 4,194,304
#define WL_XP   (128*D_INNER)         //   262,144 (96 rows padded to 128)
#define WL_DT   (D_INNER*DT_RANK)     //   131,072
#define WL_OUT  (D_MODEL*D_INNER)     // 2,097,152
#define OFF_XP  WL_IN
#define OFF_DT  (WL_IN + WL_XP)
#define OFF_OUT (WL_IN + WL_XP + WL_DT)
#define WPL     (WL_IN + WL_XP + WL_DT + WL_OUT)   // 6,684,672
#define WTOT    ((size_t)NBLK * WPL)               // 26,738,688

// ---------------- scratch (no allocation allowed) ----------------
__device__ __align__(256) float g_xz[(size_t)M_TOK*2*D_INNER];
__device__ __align__(256) float g_u[(size_t)M_TOK*D_INNER];
__device__ __align__(256) float g_xdbl[M_TOK*XD];
__device__ __align__(256) float g_part[(size_t)8*M_TOK*128];
__device__ __align__(256) float g_dt[(size_t)M_TOK*D_INNER];
// bf16 split activation buffers (hi/lo)
__device__ __align__(256) __nv_bfloat16 g_A0[(size_t)M_TOK*D_INNER];
__device__ __align__(256) __nv_bfloat16 g_A1[(size_t)M_TOK*D_INNER];
__device__ __align__(256) __nv_bfloat16 g_H0[(size_t)M_TOK*D_MODEL];
__device__ __align__(256) __nv_bfloat16 g_H1[(size_t)M_TOK*D_MODEL];
// bf16 split weight buffers: ALL layers, ALL weight types
__device__ __align__(256) __nv_bfloat16 g_W0[WTOT];
__device__ __align__(256) __nv_bfloat16 g_W1[WTOT];

__device__ __forceinline__ float siluf(float v) {
    return v / (1.f + __expf(-v));
}

__device__ __forceinline__ uint32_t smem_u32(const void* p) {
    uint32_t a;
    asm("{ .reg .u64 t; cvta.to.shared.u64 t, %1; cvt.u32.u64 %0, t; }" : "=r"(a) : "l"(p));
    return a;
}
#define SWZ128(o) ((o) ^ (((o) >> 3) & 0x70))

// ---- cp.async helpers ----
__device__ __forceinline__ void cp16(uint32_t saddr, const void* gaddr) {
    asm volatile("cp.async.cg.shared.global [%0], [%1], 16;" :: "r"(saddr), "l"(gaddr));
}
__device__ __forceinline__ void cp_commit() { asm volatile("cp.async.commit_group;"); }
template<int N> __device__ __forceinline__ void cp_wait() {
    asm volatile("cp.async.wait_group %0;" :: "n"(N));
}

// ---- ldmatrix + mma.sync ----
__device__ __forceinline__ void ldm_x4(uint32_t addr, uint32_t f[4]) {
    asm volatile("ldmatrix.sync.aligned.m8n8.x4.shared.b16 {%0,%1,%2,%3}, [%4];"
                 : "=r"(f[0]), "=r"(f[1]), "=r"(f[2]), "=r"(f[3]) : "r"(addr));
}
__device__ __forceinline__ void mma16816(float c[4], const uint32_t a[4],
                                         uint32_t b0, uint32_t b1) {
    asm volatile(
        "mma.sync.aligned.m16n8k16.row.col.f32.bf16.bf16.f32 "
        "{%0,%1,%2,%3}, {%4,%5,%6,%7}, {%8,%9}, {%0,%1,%2,%3};"
        : "+f"(c[0]), "+f"(c[1]), "+f"(c[2]), "+f"(c[3])
        : "r"(a[0]), "r"(a[1]), "r"(a[2]), "r"(a[3]), "r"(b0), "r"(b1));
}

// ================= bf16x2-split HMMA GEMM =================
//  C[M,N] = (A0+A1)[M,K] * (W0+W1)[N,K]^T, 3-term split, fp32 accum.
//  BM=BN=128, BK=64, 256 threads (8 warps: 4M x 2N).
//  3-stage cp.async ring, single __syncthreads per chunk, loads interleaved
//  with compute (CUTLASS multistage ordering).
//  EPI: 0 none, 1 softplus(x+bias[n]), 2 silu
//  OSPLIT: write hi/lo bf16 outputs instead of fp32
//  SPLITK: grid.z K-splits of size ksplit, fp32 partials at z*M*N
#define GSM_STAGE 65536            // 4 sub-tiles x 128x64 bf16 (16KB each)
#define GSM_TOTAL (3*GSM_STAGE)

template<int EPI, int OSPLIT, int SPLITK>
__global__ void __launch_bounds__(256, 1) mmagemm_k(
    const __nv_bfloat16* __restrict__ A0, const __nv_bfloat16* __restrict__ A1,
    const __nv_bfloat16* __restrict__ W0, const __nv_bfloat16* __restrict__ W1,
    const float* __restrict__ bias, float* __restrict__ C,
    __nv_bfloat16* __restrict__ Chi, __nv_bfloat16* __restrict__ Clo,
    int M, int N, int K, int ksplit)
{
    extern __shared__ char dsm[];
    const uint32_t sb = smem_u32(dsm);
    const int tid  = threadIdx.x;
    const int wid  = tid >> 5;
    const int lane = tid & 31;
    const int wm = wid & 3;
    const int wn = wid >> 2;
    const int bm = blockIdx.y * 128;
    const int bn = blockIdx.x * 128;

    int kbase = 0, Kloc = K;
    if (SPLITK) {
        kbase = blockIdx.z * ksplit;
        Kloc  = ksplit;
        C += (size_t)blockIdx.z * (size_t)M * N;
    }

    const __nv_bfloat16* gb[4] = {
        A0 + (size_t)bm * K + kbase, A1 + (size_t)bm * K + kbase,
        W0 + (size_t)bn * K + kbase, W1 + (size_t)bn * K + kbase };

    const int ch = tid & 7;          // 16B chunk in 128B row
    const int r0 = tid >> 3;         // 0..31

    // issue one of the 4 sub-tiles (A0/A1/W0/W1) of a chunk
    auto issue_quarter = [&](int kt, int stage, int buf) {
        uint32_t st = sb + stage * GSM_STAGE + buf * 16384;
        const __nv_bfloat16* g = gb[buf] + kt + ch * 8;
#pragma unroll
        for (int j = 0; j < 4; j++) {
            int row = r0 + j * 32;
            uint32_t o = (uint32_t)(row * 128 + ch * 16);
            cp16(st + SWZ128(o), g + (size_t)row * K);
        }
    };

    float acc[2][8][4];
#pragma unroll
    for (int i = 0; i < 2; i++)
#pragma unroll
        for (int j = 0; j < 8; j++)
#pragma unroll
            for (int q = 0; q < 4; q++) acc[i][j][q] = 0.f;

    const int a_row = lane & 15;
    const int a_kof = (lane >> 4) << 3;
    const int b_row = (lane & 7) + ((lane & 16) ? 8 : 0);
    const int b_kof = (lane & 8) ? 8 : 0;

    const int T = Kloc / 64;
    // prologue: 2 chunks in flight
#pragma unroll
    for (int b = 0; b < 4; b++) issue_quarter(0, 0, b);
    cp_commit();
    if (T > 1) {
#pragma unroll
        for (int b = 0; b < 4; b++) issue_quarter(64, 1, b);
        cp_commit();
    }

    for (int t = 0; t < T; t++) {
        if (t + 1 < T) cp_wait<1>();   // chunk t complete, t+1 still loading
        else           cp_wait<0>();   // tail: everything complete
        __syncthreads();               // all copies of chunk t visible; iter t-1 reads done

        const int s = t % 3;
        const uint32_t stA0 = sb + s * GSM_STAGE;
        const uint32_t stA1 = stA0 + 16384;
        const uint32_t stW0 = stA0 + 32768;
        const uint32_t stW1 = stA0 + 49152;

        const bool pf = (t + 2 < T);
        const int  ps = (t + 2) % 3;

#pragma unroll
        for (int kk = 0; kk < 4; kk++) {
            if (pf) issue_quarter((t + 2) * 64, ps, kk);   // spread loads over compute
            const int k0 = kk * 16;
            uint32_t a0f[2][4], a1f[2][4];
#pragma unroll
            for (int mt = 0; mt < 2; mt++) {
                int row = wm * 32 + mt * 16 + a_row;
                uint32_t o = (uint32_t)(row * 128 + (k0 + a_kof) * 2);
                ldm_x4(stA0 + SWZ128(o), a0f[mt]);
                ldm_x4(stA1 + SWZ128(o), a1f[mt]);
            }
#pragma unroll
            for (int nq = 0; nq < 4; nq++) {
                int nrow = wn * 64 + nq * 16 + b_row;
                uint32_t o = (uint32_t)(nrow * 128 + (k0 + b_kof) * 2);
                uint32_t w0f[4], w1f[4];
                ldm_x4(stW0 + SWZ128(o), w0f);
                ldm_x4(stW1 + SWZ128(o), w1f);
#pragma unroll
                for (int mt = 0; mt < 2; mt++)
#pragma unroll
                    for (int h = 0; h < 2; h++) {
                        float* c = acc[mt][nq * 2 + h];
                        mma16816(c, a0f[mt], w0f[2*h], w0f[2*h+1]);
                        mma16816(c, a0f[mt], w1f[2*h], w1f[2*h+1]);
                        mma16816(c, a1f[mt], w0f[2*h], w0f[2*h+1]);
                    }
            }
        }
        if (pf) cp_commit();
    }

    // ---- epilogue ----
    const int erow = lane >> 2;
    const int ecol = (lane & 3) * 2;
#pragma unroll
    for (int mt = 0; mt < 2; mt++) {
#pragma unroll
        for (int nt = 0; nt < 8; nt++) {
            int n = bn + wn * 64 + nt * 8 + ecol;
#pragma unroll
            for (int h = 0; h < 2; h++) {
                int m = bm + wm * 32 + mt * 16 + erow + h * 8;
                float vx = acc[mt][nt][2*h], vy = acc[mt][nt][2*h+1];
                if (EPI == 1) {
                    vx += bias[n]; vy += bias[n+1];
                    vx = fmaxf(vx, 0.f) + log1pf(__expf(-fabsf(vx)));
                    vy = fmaxf(vy, 0.f) + log1pf(__expf(-fabsf(vy)));
                }
                if (EPI == 2) { vx = siluf(vx); vy = siluf(vy); }
                if (OSPLIT) {
                    __nv_bfloat16 hx = __float2bfloat16(vx);
                    __nv_bfloat16 hy = __float2bfloat16(vy);
                    __nv_bfloat162 hp; hp.x = hx; hp.y = hy;
                    __nv_bfloat162 lp;
                    lp.x = __float2bfloat16(vx - __bfloat162float(hx));
                    lp.y = __float2bfloat16(vy - __bfloat162float(hy));
                    *reinterpret_cast<__nv_bfloat162*>(Chi + (size_t)m * N + n) = hp;
                    *reinterpret_cast<__nv_bfloat162*>(Clo + (size_t)m * N + n) = lp;
                } else {
                    float2 v = {vx, vy};
                    *reinterpret_cast<float2*>(C + (size_t)m * N + n) = v;
                }
            }
        }
    }
}

// ======== mega weight cvt: all layers, all types, one launch ========
__global__ void cvt_all_k(const float* __restrict__ inw, const float* __restrict__ xpw,
                          const float* __restrict__ dtw, const float* __restrict__ outw,
                          __nv_bfloat16* __restrict__ hi, __nv_bfloat16* __restrict__ lo)
{
    size_t i = (size_t)blockIdx.x * blockDim.x + threadIdx.x;   // < WTOT
    int layer = (int)(i / WPL);
    int r = (int)(i - (size_t)layer * WPL);
    float v;
    if (r < WL_IN) {
        v = inw[(size_t)layer * WL_IN + r];
    } else if (r < OFF_DT) {
        int rr = r - OFF_XP;
        int row = rr / D_INNER, col = rr - row * D_INNER;
        v = (row < XD) ? xpw[(size_t)layer * XD * D_INNER + (size_t)row * D_INNER + col] : 0.f;
    } else if (r < OFF_OUT) {
        v = dtw[(size_t)layer * WL_DT + (r - OFF_DT)];
    } else {
        v = outw[(size_t)layer * WL_OUT + (r - OFF_OUT)];
    }
    __nv_bfloat16 h = __float2bfloat16(v);
    hi[i] = h;
    lo[i] = __float2bfloat16(v - __bfloat162float(h));
}

// ================= embedding (writes split directly) =================
__global__ void embed_split_k(const float* __restrict__ x, const float* __restrict__ ew,
                              const float* __restrict__ eb,
                              __nv_bfloat16* __restrict__ hi,
                              __nv_bfloat16* __restrict__ lo)
{
    int i = blockIdx.x * blockDim.x + threadIdx.x;
    int d = i % D_MODEL, m = i / D_MODEL;
    float v = fmaf(x[m], ew[d], eb[d]);
    __nv_bfloat16 h = __float2bfloat16(v);
    hi[i] = h;
    lo[i] = __float2bfloat16(v - __bfloat162float(h));
}

// ============ causal depthwise conv + silu (fp32 + split outputs) ============
__global__ void conv_silu_k(const float* __restrict__ xz, const float* __restrict__ cw,
                            const float* __restrict__ cb, float* __restrict__ u,
                            __nv_bfloat16* __restrict__ uhi, __nv_bfloat16* __restrict__ ulo)
{
    int i = blockIdx.x * blockDim.x + threadIdx.x;
    int d = i % D_INNER;
    int m = i / D_INNER;
    int t = m % SEQLEN;
    float acc = cb[d];
#pragma unroll
    for (int k = 0; k < D_CONV; k++) {
        int tt = t - (D_CONV-1) + k;
        if (tt >= 0)
            acc = fmaf(cw[d*D_CONV + k], xz[(size_t)(m-(D_CONV-1)+k)*(2*D_INNER) + d], acc);
    }
    float v = siluf(acc);
    u[i] = v;
    __nv_bfloat16 h = __float2bfloat16(v);
    uhi[i] = h;
    ulo[i] = __float2bfloat16(v - __bfloat162float(h));
}

// ======= reduce 8 split-K partials -> xdbl fp32 + dt_lo bf16 split =======
__global__ void reduce8_k(const float* __restrict__ part,
                          float* __restrict__ xdbl,
                          __nv_bfloat16* __restrict__ dh, __nv_bfloat16* __restrict__ dl)
{
    int i = blockIdx.x * blockDim.x + threadIdx.x;   // M_TOK*96
    if (i < M_TOK * XD) {
        int m = i / XD, c = i - m * XD;
        float s = 0.f;
#pragma unroll
        for (int z = 0; z < 8; z++)
            s += part[(size_t)z * M_TOK * 128 + (size_t)m * 128 + c];
        xdbl[i] = s;
        if (c < DT_RANK) {
            __nv_bfloat16 h = __float2bfloat16(s);
            dh[(size_t)m * DT_RANK + c] = h;
            dl[(size_t)m * DT_RANK + c] = __float2bfloat16(s - __bfloat162float(h));
        }
    }
}

// ---------------- selective scan + gating fused (writes yg split) ----------------
#define SC_D 32
#define SC_T 64
__global__ void __launch_bounds__(512) scan_k(
    const float* __restrict__ dt, const float* __restrict__ u,
    const float* __restrict__ xdbl, const float* __restrict__ xz,
    const float* __restrict__ A_log, const float* __restrict__ Dp,
    __nv_bfloat16* __restrict__ yhi, __nv_bfloat16* __restrict__ ylo)
{
    __shared__ float s_dt[SC_T][SC_D];
    __shared__ float s_u [SC_T][SC_D];
    __shared__ float s_z [SC_T][SC_D];
    __shared__ float s_B [SC_T][D_STATE];
    __shared__ float s_C [SC_T][D_STATE];

    const int b  = blockIdx.y;
    const int d0 = blockIdx.x * SC_D;
    const int tid = threadIdx.x;
    const int n  = tid & 15;
    const int dl = tid >> 4;
    const int d  = d0 + dl;

    const float Aval = -__expf(A_log[d*D_STATE + n]);
    const float Dval = Dp[d];
    float s = 0.f;
    const size_t rowbase = (size_t)b * SEQLEN;

    for (int t0 = 0; t0 < SEQLEN; t0 += SC_T) {
        for (int idx = tid; idx < SC_T*SC_D; idx += 512) {
            int tl = idx / SC_D, dd = idx % SC_D;
            size_t r = rowbase + t0 + tl;
            s_dt[tl][dd] = dt[r*D_INNER + d0 + dd];
            s_u [tl][dd] = u [r*D_INNER + d0 + dd];
            s_z [tl][dd] = xz[r*(2*D_INNER) + D_INNER + d0 + dd];
        }
        for (int idx = tid; idx < SC_T*D_STATE; idx += 512) {
            int tl = idx / D_STATE, nn = idx % D_STATE;
            size_t r = rowbase + t0 + tl;
            s_B[tl][nn] = xdbl[r*XD + DT_RANK + nn];
            s_C[tl][nn] = xdbl[r*XD + DT_RANK + D_STATE + nn];
        }
        __syncthreads();

        for (int tl = 0; tl < SC_T; tl++) {
            float dtv = s_dt[tl][dl];
            float uv  = s_u [tl][dl];
            float dA  = __expf(dtv * Aval);
            s = fmaf(dA, s, dtv * uv * s_B[tl][n]);
            float y = s * s_C[tl][n];
#pragma unroll
            for (int off = 8; off; off >>= 1)
                y += __shfl_xor_sync(0xffffffffu, y, off, 16);
            if (n == 0) {
                float zv = s_z[tl][dl];
                float v  = fmaf(Dval, uv, y) * siluf(zv);
                __nv_bfloat16 h = __float2bfloat16(v);
                size_t o = (rowbase + t0 + tl)*D_INNER + d;
                yhi[o] = h;
                ylo[o] = __float2bfloat16(v - __bfloat162float(h));
            }
        }
        __syncthreads();
    }
}

// ---------------- host ----------------
extern "C" void kernel_launch(void* const* d_in, const int* in_sizes, int n_in,
                              void* d_out, int out_size)
{
    const float* x          = (const float*)d_in[0];
    const float* emb_w      = (const float*)d_in[1];
    const float* emb_b      = (const float*)d_in[2];
    const float* in_proj_w  = (const float*)d_in[3];
    const float* conv_w     = (const float*)d_in[4];
    const float* conv_b     = (const float*)d_in[5];
    const float* x_proj_w   = (const float*)d_in[6];
    const float* dt_proj_w  = (const float*)d_in[7];
    const float* dt_proj_b  = (const float*)d_in[8];
    const float* A_log      = (const float*)d_in[9];
    const float* D_param    = (const float*)d_in[10];
    const float* out_proj_w = (const float*)d_in[11];
    float* out = (float*)d_out;

    float *pxz, *pu, *pxdbl, *ppart, *pdt;
    __nv_bfloat16 *pA0, *pA1, *pH0, *pH1, *pW0, *pW1;
    cudaGetSymbolAddress((void**)&pxz,   g_xz);
    cudaGetSymbolAddress((void**)&pu,    g_u);
    cudaGetSymbolAddress((void**)&pxdbl, g_xdbl);
    cudaGetSymbolAddress((void**)&ppart, g_part);
    cudaGetSymbolAddress((void**)&pdt,   g_dt);
    cudaGetSymbolAddress((void**)&pA0,   g_A0);
    cudaGetSymbolAddress((void**)&pA1,   g_A1);
    cudaGetSymbolAddress((void**)&pH0,   g_H0);
    cudaGetSymbolAddress((void**)&pH1,   g_H1);
    cudaGetSymbolAddress((void**)&pW0,   g_W0);
    cudaGetSymbolAddress((void**)&pW1,   g_W1);

    cudaFuncSetAttribute(mmagemm_k<0,0,0>, cudaFuncAttributeMaxDynamicSharedMemorySize, GSM_TOTAL);
    cudaFuncSetAttribute(mmagemm_k<0,0,1>, cudaFuncAttributeMaxDynamicSharedMemorySize, GSM_TOTAL);
    cudaFuncSetAttribute(mmagemm_k<1,0,0>, cudaFuncAttributeMaxDynamicSharedMemorySize, GSM_TOTAL);
    cudaFuncSetAttribute(mmagemm_k<2,1,0>, cudaFuncAttributeMaxDynamicSharedMemorySize, GSM_TOTAL);
    cudaFuncSetAttribute(mmagemm_k<2,0,0>, cudaFuncAttributeMaxDynamicSharedMemorySize, GSM_TOTAL);

    // all weight conversions in one launch (WTOT divisible by 256)
    cvt_all_k<<<(unsigned)(WTOT/256), 256>>>(in_proj_w, x_proj_w, dt_proj_w, out_proj_w, pW0, pW1);

    embed_split_k<<<(M_TOK*D_MODEL)/256, 256>>>(x, emb_w, emb_b, pH0, pH1);

    for (int i = 0; i < NBLK; i++) {
        const __nv_bfloat16* w0 = pW0 + (size_t)i * WPL;
        const __nv_bfloat16* w1 = pW1 + (size_t)i * WPL;

        // --- GEMM1 (HMMA): xz = h @ in_proj_w^T  [2048 x 4096 x 1024]
        mmagemm_k<0,0,0><<<dim3((2*D_INNER)/128, M_TOK/128), 256, GSM_TOTAL>>>(
            pH0, pH1, w0, w1, nullptr, pxz, nullptr, nullptr,
            M_TOK, 2*D_INNER, D_MODEL, 0);

        // --- depthwise conv + silu -> u (fp32 + split)
        conv_silu_k<<<(M_TOK*D_INNER)/256, 256>>>(
            pxz, conv_w + (size_t)i*D_INNER*D_CONV, conv_b + (size_t)i*D_INNER,
            pu, pA0, pA1);

        // --- GEMM2 (HMMA split-K x8): x_dbl = u @ x_proj_w^T  [2048 x 96(pad128) x 2048]
        mmagemm_k<0,0,1><<<dim3(1, M_TOK/128, 8), 256, GSM_TOTAL>>>(
            pA0, pA1, w0 + OFF_XP, w1 + OFF_XP, nullptr, ppart, nullptr, nullptr,
            M_TOK, 128, D_INNER, D_INNER/8);
        reduce8_k<<<(M_TOK*XD + 255)/256, 256>>>(ppart, pxdbl, pA0, pA1);

        // --- GEMM3 (HMMA): dt = softplus(dt_lo @ dt_proj_w^T + b)  [2048 x 2048 x 64]
        mmagemm_k<1,0,0><<<dim3(D_INNER/128, M_TOK/128), 256, GSM_TOTAL>>>(
            pA0, pA1, w0 + OFF_DT, w1 + OFF_DT, dt_proj_b + (size_t)i*D_INNER,
            pdt, nullptr, nullptr, M_TOK, D_INNER, DT_RANK, 0);

        // --- selective scan + gating -> yg split
        scan_k<<<dim3(D_INNER/SC_D, BATCH), 512>>>(
            pdt, pu, pxdbl, pxz,
            A_log + (size_t)i*D_INNER*D_STATE, D_param + (size_t)i*D_INNER, pA0, pA1);

        // --- GEMM4 (HMMA): h' = silu(yg @ out_proj_w^T)  [2048 x 1024 x 2048]
        if (i == NBLK-1) {
            mmagemm_k<2,0,0><<<dim3(D_MODEL/128, M_TOK/128), 256, GSM_TOTAL>>>(
                pA0, pA1, w0 + OFF_OUT, w1 + OFF_OUT, nullptr, out, nullptr, nullptr,
                M_TOK, D_MODEL, D_INNER, 0);
        } else {
            mmagemm_k<2,1,0><<<dim3(D_MODEL/128, M_TOK/128), 256, GSM_TOTAL>>>(
                pA0, pA1, w0 + OFF_OUT, w1 + OFF_OUT, nullptr, nullptr, pH0, pH1,
                M_TOK, D_MODEL, D_INNER, 0);
        }
    }
    (void)in_sizes; (void)n_in; (void)out_size;
}